// round 1
// baseline (speedup 1.0000x reference)
#include <cuda_runtime.h>
#include <cuda_bf16.h>
#include <math.h>

// Problem dims
#define S_  1024
#define B_  4
#define D_  768
#define NH_ 12
#define DH_ 64
#define L_  4
#define DI_ 3072
#define SB_ (S_*B_)

// ---------------- scratch (device globals; no allocation allowed) ------------
__device__ float g_h[SB_*D_];
__device__ float g_q[SB_*D_];
__device__ float g_kv[SB_*2*D_];
__device__ float g_attn[SB_*D_];
__device__ float g_content[SB_*D_];
__device__ float g_cK[SB_*D_];
__device__ float g_diff[SB_*D_];
__device__ float g_ff[SB_*DI_];
__device__ float g_out1[SB_*D_];

// ---------------- embedding + sinusoidal positional encoding -----------------
__global__ void embed_kernel(const int* __restrict__ inp,
                             const float* __restrict__ we,
                             float* __restrict__ h)
{
    int row = blockIdx.x;          // row = s*B + b
    int s = row / B_;
    int b = row % B_;
    int t = threadIdx.x;           // 256
    int tok = inp[s*B_ + b];
    float pos = (float)(S_ - 1 - s);
    const float lg = logf(10000.0f);
    for (int d = t; d < D_; d += 256) {
        int i = (d < 384) ? d : d - 384;
        float freq = expf(-((float)(2*i) / (float)D_) * lg);
        float ang = pos * freq;
        float pe = (d < 384) ? sinf(ang) : cosf(ang);
        h[(size_t)row*D_ + d] = we[(size_t)tok*D_ + d] * 27.712812921102035f + pe;
    }
}

// ---------------- NT GEMM: C[M,N] = A[M,K] @ B[N,K]^T (+epilogue) ------------
// epi: 0 = none, 1 = bias+relu, 2 = bias
__global__ __launch_bounds__(256) void gemm_nt(
    const float* __restrict__ A, const float* __restrict__ Bm,
    const float* __restrict__ bias, float* __restrict__ C,
    int M, int N, int K, int epi)
{
    __shared__ float As[64][17];
    __shared__ float Bs[64][17];
    int tid = threadIdx.x;
    int m0 = blockIdx.y * 64, n0 = blockIdx.x * 64;
    int r  = tid >> 2;
    int c4 = (tid & 3) * 4;
    int tx = tid & 15, ty = tid >> 4;
    float acc[4][4] = {};
    for (int k0 = 0; k0 < K; k0 += 16) {
        float4 av = *(const float4*)(A  + (size_t)(m0 + r)*K + k0 + c4);
        float4 bv = *(const float4*)(Bm + (size_t)(n0 + r)*K + k0 + c4);
        As[r][c4+0] = av.x; As[r][c4+1] = av.y; As[r][c4+2] = av.z; As[r][c4+3] = av.w;
        Bs[r][c4+0] = bv.x; Bs[r][c4+1] = bv.y; Bs[r][c4+2] = bv.z; Bs[r][c4+3] = bv.w;
        __syncthreads();
        #pragma unroll
        for (int kk = 0; kk < 16; kk++) {
            float a[4], b[4];
            #pragma unroll
            for (int u = 0; u < 4; u++) { a[u] = As[ty*4+u][kk]; b[u] = Bs[tx*4+u][kk]; }
            #pragma unroll
            for (int i = 0; i < 4; i++)
                #pragma unroll
                for (int j = 0; j < 4; j++)
                    acc[i][j] = fmaf(a[i], b[j], acc[i][j]);
        }
        __syncthreads();
    }
    #pragma unroll
    for (int i = 0; i < 4; i++) {
        int m = m0 + ty*4 + i;
        #pragma unroll
        for (int j = 0; j < 4; j++) {
            int n = n0 + tx*4 + j;
            float cv = acc[i][j];
            if (epi == 1)      cv = fmaxf(cv + bias[n], 0.f);
            else if (epi == 2) cv = cv + bias[n];
            C[(size_t)m*N + n] = cv;
        }
    }
}

// ---------------- causal attention: one block per (query i, b, n) ------------
__global__ __launch_bounds__(128) void attn_kernel(
    const float* __restrict__ q, const float* __restrict__ k,
    const float* __restrict__ v, float* __restrict__ o,
    int qS, int kvS, int oS)
{
    int i  = blockIdx.x;
    int bn = blockIdx.y;
    int b = bn / NH_, n = bn % NH_;
    int col = n * DH_;
    int t = threadIdx.x;

    __shared__ float sc[S_];
    __shared__ __align__(16) float qs[DH_];
    __shared__ float red[128];

    if (t < DH_) qs[t] = q[(size_t)(i*B_ + b)*qS + col + t];
    __syncthreads();

    float lmax = -3.4e38f;
    const float4* q4 = (const float4*)qs;
    for (int j = t; j <= i; j += 128) {
        const float4* kr = (const float4*)(k + (size_t)(j*B_ + b)*kvS + col);
        float dot = 0.f;
        #pragma unroll
        for (int c = 0; c < 16; c++) {
            float4 kv4 = kr[c]; float4 qv = q4[c];
            dot += kv4.x*qv.x + kv4.y*qv.y + kv4.z*qv.z + kv4.w*qv.w;
        }
        dot *= 0.125f;   // 1/sqrt(64)
        sc[j] = dot;
        lmax = fmaxf(lmax, dot);
    }
    red[t] = lmax; __syncthreads();
    for (int s = 64; s > 0; s >>= 1) { if (t < s) red[t] = fmaxf(red[t], red[t+s]); __syncthreads(); }
    float mx = red[0]; __syncthreads();

    float lsum = 0.f;
    for (int j = t; j <= i; j += 128) { float e = expf(sc[j] - mx); sc[j] = e; lsum += e; }
    red[t] = lsum; __syncthreads();
    for (int s = 64; s > 0; s >>= 1) { if (t < s) red[t] += red[t+s]; __syncthreads(); }
    float inv = 1.f / red[0];
    __syncthreads();

    int d = t & 63, half = t >> 6;
    float acc = 0.f;
    for (int j = half; j <= i; j += 2)
        acc += sc[j] * v[(size_t)(j*B_ + b)*kvS + col + d];
    red[t] = acc; __syncthreads();
    if (t < DH_)
        o[(size_t)(i*B_ + b)*oS + col + t] = (red[t] + red[t + 64]) * inv;
}

// -------- memory retrieval + delta: content, diff = k - delta, cK ------------
__global__ __launch_bounds__(256) void mem_retrieve(
    const float* __restrict__ q, const float* __restrict__ kp,
    const float* __restrict__ vp, const float* __restrict__ memory,
    const float* __restrict__ mem_norm, int l,
    float* __restrict__ content, float* __restrict__ diff, float* __restrict__ cKout,
    int qS, int kvS)
{
    int bn = blockIdx.x;
    int b = bn / NH_, n = bn % NH_;
    int chunk = blockIdx.y;          // 8 chunks of 128 s-values
    int t = threadIdx.x;

    __shared__ float Msh[DH_][DH_+1];
    __shared__ float normsh[DH_];
    __shared__ float cqsh[4][DH_];
    __shared__ float cksh[4][DH_];

    const float* Mg = memory + ((size_t)(l*B_ + b)*NH_ + n)*DH_*DH_;
    for (int idx = t; idx < DH_*DH_; idx += 256) Msh[idx >> 6][idx & 63] = Mg[idx];
    if (t < DH_) normsh[t] = mem_norm[((size_t)(l*B_ + b)*NH_ + n)*DH_ + t];
    __syncthreads();

    int g = t >> 6, d = t & 63;
    int col = n * DH_;
    for (int it = 0; it < 32; ++it) {
        int s = chunk*128 + it*4 + g;
        size_t row = (size_t)(s*B_ + b);
        float qv = q [row*qS  + col + d];
        float vv = vp[row*kvS + col + d];
        float cq = qv > 0.f ? qv + 1.f : expf(qv);
        float ck = vv > 0.f ? vv + 1.f : expf(vv);
        cqsh[g][d] = cq; cksh[g][d] = ck;
        __syncthreads();
        float accA = 0.f, accB = 0.f, denQ = 0.f, denK = 0.f;
        #pragma unroll 8
        for (int kk = 0; kk < DH_; kk++) {
            float mq = Msh[kk][d];
            accA += cqsh[g][kk] * mq;
            accB += cksh[g][kk] * mq;
            denQ += cqsh[g][kk] * normsh[kk];
            denK += cksh[g][kk] * normsh[kk];
        }
        size_t oidx = row*D_ + col + d;
        content[oidx] = accA / denQ;
        diff[oidx]    = kp[row*kvS + col + d] - accB / denK;
        cKout[oidx]   = ck;
        __syncthreads();
    }
}

// -------- memory update: newM[k][v] = M[k][v] + sum_s cK[s,k]*diff[s,v] ------
__global__ __launch_bounds__(256) void mem_update(
    const float* __restrict__ cK, const float* __restrict__ diff,
    const float* __restrict__ memory, int l, float* __restrict__ outM)
{
    int bn = blockIdx.x;
    int b = bn / NH_, n = bn % NH_;
    __shared__ float aS[16][DH_];
    __shared__ float bS[16][DH_];
    int t = threadIdx.x;
    int tx = t & 15, ty = t >> 4;
    float acc[4][4] = {};
    int col = n * DH_;
    int r  = t >> 4;
    int c4 = (t & 15) * 4;
    for (int s0 = 0; s0 < S_; s0 += 16) {
        size_t row = (size_t)((s0 + r)*B_ + b);
        *(float4*)&aS[r][c4] = *(const float4*)(cK   + row*D_ + col + c4);
        *(float4*)&bS[r][c4] = *(const float4*)(diff + row*D_ + col + c4);
        __syncthreads();
        #pragma unroll
        for (int ss = 0; ss < 16; ss++) {
            float a[4], bb[4];
            #pragma unroll
            for (int u = 0; u < 4; u++) { a[u] = aS[ss][ty*4+u]; bb[u] = bS[ss][tx*4+u]; }
            #pragma unroll
            for (int i = 0; i < 4; i++)
                #pragma unroll
                for (int j = 0; j < 4; j++)
                    acc[i][j] = fmaf(a[i], bb[j], acc[i][j]);
        }
        __syncthreads();
    }
    const float* Mg = memory + ((size_t)(l*B_ + b)*NH_ + n)*DH_*DH_;
    float*       Og = outM   + ((size_t)(l*B_ + b)*NH_ + n)*DH_*DH_;
    #pragma unroll
    for (int i = 0; i < 4; i++)
        #pragma unroll
        for (int j = 0; j < 4; j++) {
            int kk = ty*4 + i, vv = tx*4 + j;
            Og[kk*DH_ + vv] = Mg[kk*DH_ + vv] + acc[i][j];
        }
}

// -------- norm update: outN = mem_norm + sum_s cK -----------------------------
__global__ void norm_update(const float* __restrict__ cK,
                            const float* __restrict__ mem_norm, int l,
                            float* __restrict__ outN)
{
    int bn = blockIdx.x;
    int b = bn / NH_, n = bn % NH_;
    int t = threadIdx.x;   // 64
    int col = n * DH_;
    float acc = 0.f;
    for (int s = 0; s < S_; s++) acc += cK[(size_t)(s*B_ + b)*D_ + col + t];
    size_t o = ((size_t)(l*B_ + b)*NH_ + n)*DH_ + t;
    outN[o] = mem_norm[o] + acc;
}

// -------- gated combine: attn = gate*content + (1-gate)*attn ------------------
__global__ void combine_kernel(float* __restrict__ attn,
                               const float* __restrict__ content,
                               float gate, int nElem)
{
    int i = blockIdx.x * blockDim.x + threadIdx.x;
    if (i < nElem) attn[i] = gate * content[i] + (1.f - gate) * attn[i];
}

// -------- layernorm with residual: out = LN(res + y) --------------------------
__global__ __launch_bounds__(256) void ln_kernel(
    const float* __restrict__ res, const float* __restrict__ y,
    const float* __restrict__ g, const float* __restrict__ bb,
    float* __restrict__ out)
{
    int row = blockIdx.x;
    int t = threadIdx.x;
    __shared__ float red[256];
    size_t base = (size_t)row * D_;
    float x0 = res[base + t      ] + y[base + t      ];
    float x1 = res[base + t + 256] + y[base + t + 256];
    float x2 = res[base + t + 512] + y[base + t + 512];
    red[t] = x0 + x1 + x2; __syncthreads();
    for (int o = 128; o > 0; o >>= 1) { if (t < o) red[t] += red[t+o]; __syncthreads(); }
    float mu = red[0] * (1.f / 768.f); __syncthreads();
    float d0 = x0 - mu, d1 = x1 - mu, d2 = x2 - mu;
    red[t] = d0*d0 + d1*d1 + d2*d2; __syncthreads();
    for (int o = 128; o > 0; o >>= 1) { if (t < o) red[t] += red[t+o]; __syncthreads(); }
    float inv = rsqrtf(red[0] * (1.f / 768.f) + 1e-5f);
    out[base + t      ] = d0 * inv * g[t      ] + bb[t      ];
    out[base + t + 256] = d1 * inv * g[t + 256] + bb[t + 256];
    out[base + t + 512] = d2 * inv * g[t + 512] + bb[t + 512];
}

// ------------------------------- launcher -------------------------------------
extern "C" void kernel_launch(void* const* d_in, const int* in_sizes, int n_in,
                              void* d_out, int out_size)
{
    const int*   inp      = (const int*)  d_in[0];
    const float* word_emb = (const float*)d_in[1];
    const float* Wq       = (const float*)d_in[2];
    const float* Wkv      = (const float*)d_in[3];
    const float* Wo       = (const float*)d_in[4];
    const float* ln1g     = (const float*)d_in[5];
    const float* ln1b     = (const float*)d_in[6];
    const float* ffW1     = (const float*)d_in[7];
    const float* ffb1     = (const float*)d_in[8];
    const float* ffW2     = (const float*)d_in[9];
    const float* ffb2     = (const float*)d_in[10];
    const float* ln2g     = (const float*)d_in[11];
    const float* ln2b     = (const float*)d_in[12];
    const float* memory   = (const float*)d_in[13];
    const float* mem_norm = (const float*)d_in[14];

    float* out  = (float*)d_out;
    float* outH = out;                         // (S,B,D)
    float* outM = out + (size_t)SB_*D_;        // (L,B,NH,DH,DH)
    float* outN = outM + (size_t)L_*B_*NH_*DH_*DH_;  // (L,B,NH,DH)

    float *h, *q, *kv, *attn, *content, *cK, *diff, *ff, *out1;
    cudaGetSymbolAddress((void**)&h,       g_h);
    cudaGetSymbolAddress((void**)&q,       g_q);
    cudaGetSymbolAddress((void**)&kv,      g_kv);
    cudaGetSymbolAddress((void**)&attn,    g_attn);
    cudaGetSymbolAddress((void**)&content, g_content);
    cudaGetSymbolAddress((void**)&cK,      g_cK);
    cudaGetSymbolAddress((void**)&diff,    g_diff);
    cudaGetSymbolAddress((void**)&ff,      g_ff);
    cudaGetSymbolAddress((void**)&out1,    g_out1);

    const float gate = 1.0f / (1.0f + expf(-0.01f));

    embed_kernel<<<SB_, 256>>>(inp, word_emb, h);

    for (int l = 0; l < L_; l++) {
        // q = h @ Wq^T   (4096 x 768 x 768)
        gemm_nt<<<dim3(D_/64, SB_/64), 256>>>(h, Wq + (size_t)l*D_*D_, nullptr, q,
                                              SB_, D_, D_, 0);
        // kv = h @ Wkv^T (4096 x 1536 x 768)
        gemm_nt<<<dim3(2*D_/64, SB_/64), 256>>>(h, Wkv + (size_t)l*2*D_*D_, nullptr, kv,
                                                SB_, 2*D_, D_, 0);
        // local causal attention
        attn_kernel<<<dim3(S_, B_*NH_), 128>>>(q, kv /*k*/, kv + D_ /*v*/, attn,
                                               D_, 2*D_, D_);
        // memory retrieval + delta (content, diff, cK)
        mem_retrieve<<<dim3(B_*NH_, 8), 256>>>(q, kv /*k*/, kv + D_ /*v*/,
                                               memory, mem_norm, l,
                                               content, diff, cK, D_, 2*D_);
        // memory + norm updates straight into d_out
        mem_update<<<B_*NH_, 256>>>(cK, diff, memory, l, outM);
        norm_update<<<B_*NH_, 64>>>(cK, mem_norm, l, outN);
        // gated injection
        combine_kernel<<<(SB_*D_ + 255)/256, 256>>>(attn, content, gate, SB_*D_);
        // Wo projection (reuse content buffer as output)
        gemm_nt<<<dim3(D_/64, SB_/64), 256>>>(attn, Wo + (size_t)l*D_*D_, nullptr, content,
                                              SB_, D_, D_, 0);
        // ln1: out1 = LN(h + proj)
        ln_kernel<<<SB_, 256>>>(h, content, ln1g + l*D_, ln1b + l*D_, out1);
        // ff1 = relu(out1 @ W1^T + b1)  (4096 x 3072 x 768)
        gemm_nt<<<dim3(DI_/64, SB_/64), 256>>>(out1, ffW1 + (size_t)l*DI_*D_, ffb1 + l*DI_,
                                               ff, SB_, DI_, D_, 1);
        // ff2 = ff1 @ W2^T + b2         (4096 x 768 x 3072) -> reuse content
        gemm_nt<<<dim3(D_/64, SB_/64), 256>>>(ff, ffW2 + (size_t)l*D_*DI_, ffb2 + l*D_,
                                              content, SB_, D_, DI_, 2);
        // ln2: h = LN(out1 + ff2)
        ln_kernel<<<SB_, 256>>>(out1, content, ln2g + l*D_, ln2b + l*D_, h);
    }

    cudaMemcpyAsync(outH, h, (size_t)SB_*D_*sizeof(float),
                    cudaMemcpyDeviceToDevice);
}

// round 2
// speedup vs baseline: 1.1385x; 1.1385x over previous
#include <cuda_runtime.h>
#include <cuda_bf16.h>
#include <math.h>

// Problem dims
#define S_  1024
#define B_  4
#define D_  768
#define NH_ 12
#define DH_ 64
#define L_  4
#define DI_ 3072
#define SB_ (S_*B_)

// ---------------- scratch (device globals; no allocation allowed) ------------
__device__ float g_h[SB_*D_];
__device__ float g_q[SB_*D_];
__device__ float g_kv[SB_*2*D_];
__device__ float g_attn[SB_*D_];
__device__ float g_content[SB_*D_];
__device__ float g_cK[SB_*D_];
__device__ float g_diff[SB_*D_];
__device__ float g_ff[SB_*DI_];
__device__ float g_out1[SB_*D_];

// ---------------- embedding + sinusoidal positional encoding -----------------
__global__ void embed_kernel(const int* __restrict__ inp,
                             const float* __restrict__ we,
                             float* __restrict__ h)
{
    int row = blockIdx.x;          // row = s*B + b
    int s = row / B_;
    int b = row % B_;
    int t = threadIdx.x;           // 256
    int tok = inp[s*B_ + b];
    float pos = (float)(S_ - 1 - s);
    const float lg = logf(10000.0f);
    for (int d = t; d < D_; d += 256) {
        int i = (d < 384) ? d : d - 384;
        float freq = expf(-((float)(2*i) / (float)D_) * lg);
        float ang = pos * freq;
        float pe = (d < 384) ? sinf(ang) : cosf(ang);
        h[(size_t)row*D_ + d] = we[(size_t)tok*D_ + d] * 27.712812921102035f + pe;
    }
}

// ---------------- NT GEMM: C[M,N] = A[M,K] @ B[N,K]^T (+epilogue) ------------
// 128x128 tile, K-tile 8, 256 threads, 8x8 per thread, double-buffered SMEM.
// epi: 0 = none, 1 = bias+relu, 2 = bias
#define TP 132   // padded row (132*4 bytes = 528, 16B aligned)
__global__ __launch_bounds__(256) void gemm_nt(
    const float* __restrict__ A, const float* __restrict__ Bm,
    const float* __restrict__ bias, float* __restrict__ C,
    int M, int N, int K, int epi)
{
    __shared__ float As[2][8][TP];
    __shared__ float Bs[2][8][TP];
    int tid = threadIdx.x;
    int m0 = blockIdx.y * 128, n0 = blockIdx.x * 128;

    int lr = tid >> 1;           // 0..127: row within tile
    int lk = (tid & 1) * 4;      // 0 or 4: k offset
    const float* Aptr = A  + (size_t)(m0 + lr)*K + lk;
    const float* Bptr = Bm + (size_t)(n0 + lr)*K + lk;

    int tx = tid & 15, ty = tid >> 4;

    float acc[8][8] = {};

    // prologue: load k-tile 0
    float4 pa = *(const float4*)Aptr;
    float4 pb = *(const float4*)Bptr;
    As[0][lk+0][lr] = pa.x; As[0][lk+1][lr] = pa.y;
    As[0][lk+2][lr] = pa.z; As[0][lk+3][lr] = pa.w;
    Bs[0][lk+0][lr] = pb.x; Bs[0][lk+1][lr] = pb.y;
    Bs[0][lk+2][lr] = pb.z; Bs[0][lk+3][lr] = pb.w;
    __syncthreads();

    int buf = 0;
    for (int k0 = 8; k0 < K + 8; k0 += 8) {
        bool more = (k0 < K);
        if (more) {
            pa = *(const float4*)(Aptr + k0);
            pb = *(const float4*)(Bptr + k0);
        }
        #pragma unroll
        for (int kk = 0; kk < 8; kk++) {
            float4 a0 = *(const float4*)&As[buf][kk][ty*4];
            float4 a1 = *(const float4*)&As[buf][kk][ty*4 + 64];
            float4 b0 = *(const float4*)&Bs[buf][kk][tx*4];
            float4 b1 = *(const float4*)&Bs[buf][kk][tx*4 + 64];
            float a[8] = {a0.x,a0.y,a0.z,a0.w, a1.x,a1.y,a1.z,a1.w};
            float b[8] = {b0.x,b0.y,b0.z,b0.w, b1.x,b1.y,b1.z,b1.w};
            #pragma unroll
            for (int i = 0; i < 8; i++)
                #pragma unroll
                for (int j = 0; j < 8; j++)
                    acc[i][j] = fmaf(a[i], b[j], acc[i][j]);
        }
        if (more) {
            int nb = buf ^ 1;
            As[nb][lk+0][lr] = pa.x; As[nb][lk+1][lr] = pa.y;
            As[nb][lk+2][lr] = pa.z; As[nb][lk+3][lr] = pa.w;
            Bs[nb][lk+0][lr] = pb.x; Bs[nb][lk+1][lr] = pb.y;
            Bs[nb][lk+2][lr] = pb.z; Bs[nb][lk+3][lr] = pb.w;
            __syncthreads();
            buf = nb;
        }
    }

    // epilogue: 8x8 per thread as 2x2 blocks of 4x4, float4 stores
    #pragma unroll
    for (int ih = 0; ih < 2; ih++) {
        #pragma unroll
        for (int i = 0; i < 4; i++) {
            int m = m0 + ty*4 + ih*64 + i;
            #pragma unroll
            for (int jh = 0; jh < 2; jh++) {
                int n = n0 + tx*4 + jh*64;
                float4 cv;
                cv.x = acc[ih*4+i][jh*4+0];
                cv.y = acc[ih*4+i][jh*4+1];
                cv.z = acc[ih*4+i][jh*4+2];
                cv.w = acc[ih*4+i][jh*4+3];
                if (epi == 1) {
                    cv.x = fmaxf(cv.x + bias[n+0], 0.f);
                    cv.y = fmaxf(cv.y + bias[n+1], 0.f);
                    cv.z = fmaxf(cv.z + bias[n+2], 0.f);
                    cv.w = fmaxf(cv.w + bias[n+3], 0.f);
                } else if (epi == 2) {
                    cv.x += bias[n+0]; cv.y += bias[n+1];
                    cv.z += bias[n+2]; cv.w += bias[n+3];
                }
                *(float4*)(C + (size_t)m*N + n) = cv;
            }
        }
    }
}

// ---------------- causal attention: one block per (query i, b, n) ------------
__global__ __launch_bounds__(128) void attn_kernel(
    const float* __restrict__ q, const float* __restrict__ k,
    const float* __restrict__ v, float* __restrict__ o,
    int qS, int kvS, int oS)
{
    int i  = blockIdx.x;
    int bn = blockIdx.y;
    int b = bn / NH_, n = bn % NH_;
    int col = n * DH_;
    int t = threadIdx.x;

    __shared__ float sc[S_];
    __shared__ __align__(16) float qs[DH_];
    __shared__ float red[128];

    if (t < DH_) qs[t] = q[(size_t)(i*B_ + b)*qS + col + t];
    __syncthreads();

    float lmax = -3.4e38f;
    const float4* q4 = (const float4*)qs;
    for (int j = t; j <= i; j += 128) {
        const float4* kr = (const float4*)(k + (size_t)(j*B_ + b)*kvS + col);
        float dot = 0.f;
        #pragma unroll
        for (int c = 0; c < 16; c++) {
            float4 kv4 = kr[c]; float4 qv = q4[c];
            dot += kv4.x*qv.x + kv4.y*qv.y + kv4.z*qv.z + kv4.w*qv.w;
        }
        dot *= 0.125f;   // 1/sqrt(64)
        sc[j] = dot;
        lmax = fmaxf(lmax, dot);
    }
    red[t] = lmax; __syncthreads();
    for (int s = 64; s > 0; s >>= 1) { if (t < s) red[t] = fmaxf(red[t], red[t+s]); __syncthreads(); }
    float mx = red[0]; __syncthreads();

    float lsum = 0.f;
    for (int j = t; j <= i; j += 128) { float e = expf(sc[j] - mx); sc[j] = e; lsum += e; }
    red[t] = lsum; __syncthreads();
    for (int s = 64; s > 0; s >>= 1) { if (t < s) red[t] += red[t+s]; __syncthreads(); }
    float inv = 1.f / red[0];
    __syncthreads();

    int d = t & 63, half = t >> 6;
    float acc = 0.f;
    for (int j = half; j <= i; j += 2)
        acc += sc[j] * v[(size_t)(j*B_ + b)*kvS + col + d];
    red[t] = acc; __syncthreads();
    if (t < DH_)
        o[(size_t)(i*B_ + b)*oS + col + t] = (red[t] + red[t + 64]) * inv;
}

// -------- memory retrieval + delta: content, diff = k - delta, cK ------------
__global__ __launch_bounds__(256) void mem_retrieve(
    const float* __restrict__ q, const float* __restrict__ kp,
    const float* __restrict__ vp, const float* __restrict__ memory,
    const float* __restrict__ mem_norm, int l,
    float* __restrict__ content, float* __restrict__ diff, float* __restrict__ cKout,
    int qS, int kvS)
{
    int bn = blockIdx.x;
    int b = bn / NH_, n = bn % NH_;
    int chunk = blockIdx.y;          // 8 chunks of 128 s-values
    int t = threadIdx.x;

    __shared__ float Msh[DH_][DH_+1];
    __shared__ float normsh[DH_];
    __shared__ float cqsh[4][DH_];
    __shared__ float cksh[4][DH_];

    const float* Mg = memory + ((size_t)(l*B_ + b)*NH_ + n)*DH_*DH_;
    for (int idx = t; idx < DH_*DH_; idx += 256) Msh[idx >> 6][idx & 63] = Mg[idx];
    if (t < DH_) normsh[t] = mem_norm[((size_t)(l*B_ + b)*NH_ + n)*DH_ + t];
    __syncthreads();

    int g = t >> 6, d = t & 63;
    int col = n * DH_;
    for (int it = 0; it < 32; ++it) {
        int s = chunk*128 + it*4 + g;
        size_t row = (size_t)(s*B_ + b);
        float qv = q [row*qS  + col + d];
        float vv = vp[row*kvS + col + d];
        float cq = qv > 0.f ? qv + 1.f : expf(qv);
        float ck = vv > 0.f ? vv + 1.f : expf(vv);
        cqsh[g][d] = cq; cksh[g][d] = ck;
        __syncthreads();
        float accA = 0.f, accB = 0.f, denQ = 0.f, denK = 0.f;
        #pragma unroll 8
        for (int kk = 0; kk < DH_; kk++) {
            float mq = Msh[kk][d];
            accA += cqsh[g][kk] * mq;
            accB += cksh[g][kk] * mq;
            denQ += cqsh[g][kk] * normsh[kk];
            denK += cksh[g][kk] * normsh[kk];
        }
        size_t oidx = row*D_ + col + d;
        content[oidx] = accA / denQ;
        diff[oidx]    = kp[row*kvS + col + d] - accB / denK;
        cKout[oidx]   = ck;
        __syncthreads();
    }
}

// -------- memory update: newM[k][v] = M[k][v] + sum_s cK[s,k]*diff[s,v] ------
__global__ __launch_bounds__(256) void mem_update(
    const float* __restrict__ cK, const float* __restrict__ diff,
    const float* __restrict__ memory, int l, float* __restrict__ outM)
{
    int bn = blockIdx.x;
    int b = bn / NH_, n = bn % NH_;
    __shared__ float aS[16][DH_];
    __shared__ float bS[16][DH_];
    int t = threadIdx.x;
    int tx = t & 15, ty = t >> 4;
    float acc[4][4] = {};
    int col = n * DH_;
    int r  = t >> 4;
    int c4 = (t & 15) * 4;
    for (int s0 = 0; s0 < S_; s0 += 16) {
        size_t row = (size_t)((s0 + r)*B_ + b);
        *(float4*)&aS[r][c4] = *(const float4*)(cK   + row*D_ + col + c4);
        *(float4*)&bS[r][c4] = *(const float4*)(diff + row*D_ + col + c4);
        __syncthreads();
        #pragma unroll
        for (int ss = 0; ss < 16; ss++) {
            float a[4], bb[4];
            #pragma unroll
            for (int u = 0; u < 4; u++) { a[u] = aS[ss][ty*4+u]; bb[u] = bS[ss][tx*4+u]; }
            #pragma unroll
            for (int i = 0; i < 4; i++)
                #pragma unroll
                for (int j = 0; j < 4; j++)
                    acc[i][j] = fmaf(a[i], bb[j], acc[i][j]);
        }
        __syncthreads();
    }
    const float* Mg = memory + ((size_t)(l*B_ + b)*NH_ + n)*DH_*DH_;
    float*       Og = outM   + ((size_t)(l*B_ + b)*NH_ + n)*DH_*DH_;
    #pragma unroll
    for (int i = 0; i < 4; i++)
        #pragma unroll
        for (int j = 0; j < 4; j++) {
            int kk = ty*4 + i, vv = tx*4 + j;
            Og[kk*DH_ + vv] = Mg[kk*DH_ + vv] + acc[i][j];
        }
}

// -------- norm update: outN = mem_norm + sum_s cK -----------------------------
__global__ void norm_update(const float* __restrict__ cK,
                            const float* __restrict__ mem_norm, int l,
                            float* __restrict__ outN)
{
    int bn = blockIdx.x;
    int b = bn / NH_, n = bn % NH_;
    int t = threadIdx.x;   // 64
    int col = n * DH_;
    float acc = 0.f;
    for (int s = 0; s < S_; s++) acc += cK[(size_t)(s*B_ + b)*D_ + col + t];
    size_t o = ((size_t)(l*B_ + b)*NH_ + n)*DH_ + t;
    outN[o] = mem_norm[o] + acc;
}

// -------- gated combine: attn = gate*content + (1-gate)*attn ------------------
__global__ void combine_kernel(float* __restrict__ attn,
                               const float* __restrict__ content,
                               float gate, int nElem)
{
    int i = blockIdx.x * blockDim.x + threadIdx.x;
    if (i < nElem) attn[i] = gate * content[i] + (1.f - gate) * attn[i];
}

// -------- layernorm with residual: out = LN(res + y) --------------------------
__global__ __launch_bounds__(256) void ln_kernel(
    const float* __restrict__ res, const float* __restrict__ y,
    const float* __restrict__ g, const float* __restrict__ bb,
    float* __restrict__ out)
{
    int row = blockIdx.x;
    int t = threadIdx.x;
    __shared__ float red[256];
    size_t base = (size_t)row * D_;
    float x0 = res[base + t      ] + y[base + t      ];
    float x1 = res[base + t + 256] + y[base + t + 256];
    float x2 = res[base + t + 512] + y[base + t + 512];
    red[t] = x0 + x1 + x2; __syncthreads();
    for (int o = 128; o > 0; o >>= 1) { if (t < o) red[t] += red[t+o]; __syncthreads(); }
    float mu = red[0] * (1.f / 768.f); __syncthreads();
    float d0 = x0 - mu, d1 = x1 - mu, d2 = x2 - mu;
    red[t] = d0*d0 + d1*d1 + d2*d2; __syncthreads();
    for (int o = 128; o > 0; o >>= 1) { if (t < o) red[t] += red[t+o]; __syncthreads(); }
    float inv = rsqrtf(red[0] * (1.f / 768.f) + 1e-5f);
    out[base + t      ] = d0 * inv * g[t      ] + bb[t      ];
    out[base + t + 256] = d1 * inv * g[t + 256] + bb[t + 256];
    out[base + t + 512] = d2 * inv * g[t + 512] + bb[t + 512];
}

// ------------------------------- launcher -------------------------------------
extern "C" void kernel_launch(void* const* d_in, const int* in_sizes, int n_in,
                              void* d_out, int out_size)
{
    const int*   inp      = (const int*)  d_in[0];
    const float* word_emb = (const float*)d_in[1];
    const float* Wq       = (const float*)d_in[2];
    const float* Wkv      = (const float*)d_in[3];
    const float* Wo       = (const float*)d_in[4];
    const float* ln1g     = (const float*)d_in[5];
    const float* ln1b     = (const float*)d_in[6];
    const float* ffW1     = (const float*)d_in[7];
    const float* ffb1     = (const float*)d_in[8];
    const float* ffW2     = (const float*)d_in[9];
    const float* ffb2     = (const float*)d_in[10];
    const float* ln2g     = (const float*)d_in[11];
    const float* ln2b     = (const float*)d_in[12];
    const float* memory   = (const float*)d_in[13];
    const float* mem_norm = (const float*)d_in[14];

    float* out  = (float*)d_out;
    float* outH = out;                         // (S,B,D)
    float* outM = out + (size_t)SB_*D_;        // (L,B,NH,DH,DH)
    float* outN = outM + (size_t)L_*B_*NH_*DH_*DH_;  // (L,B,NH,DH)

    float *h, *q, *kv, *attn, *content, *cK, *diff, *ff, *out1;
    cudaGetSymbolAddress((void**)&h,       g_h);
    cudaGetSymbolAddress((void**)&q,       g_q);
    cudaGetSymbolAddress((void**)&kv,      g_kv);
    cudaGetSymbolAddress((void**)&attn,    g_attn);
    cudaGetSymbolAddress((void**)&content, g_content);
    cudaGetSymbolAddress((void**)&cK,      g_cK);
    cudaGetSymbolAddress((void**)&diff,    g_diff);
    cudaGetSymbolAddress((void**)&ff,      g_ff);
    cudaGetSymbolAddress((void**)&out1,    g_out1);

    const float gate = 1.0f / (1.0f + expf(-0.01f));

    embed_kernel<<<SB_, 256>>>(inp, word_emb, h);

    for (int l = 0; l < L_; l++) {
        // q = h @ Wq^T   (4096 x 768 x 768)
        gemm_nt<<<dim3(D_/128, SB_/128), 256>>>(h, Wq + (size_t)l*D_*D_, nullptr, q,
                                                SB_, D_, D_, 0);
        // kv = h @ Wkv^T (4096 x 1536 x 768)
        gemm_nt<<<dim3(2*D_/128, SB_/128), 256>>>(h, Wkv + (size_t)l*2*D_*D_, nullptr, kv,
                                                  SB_, 2*D_, D_, 0);
        // local causal attention
        attn_kernel<<<dim3(S_, B_*NH_), 128>>>(q, kv /*k*/, kv + D_ /*v*/, attn,
                                               D_, 2*D_, D_);
        // memory retrieval + delta (content, diff, cK)
        mem_retrieve<<<dim3(B_*NH_, 8), 256>>>(q, kv /*k*/, kv + D_ /*v*/,
                                               memory, mem_norm, l,
                                               content, diff, cK, D_, 2*D_);
        // memory + norm updates straight into d_out
        mem_update<<<B_*NH_, 256>>>(cK, diff, memory, l, outM);
        norm_update<<<B_*NH_, 64>>>(cK, mem_norm, l, outN);
        // gated injection
        combine_kernel<<<(SB_*D_ + 255)/256, 256>>>(attn, content, gate, SB_*D_);
        // Wo projection (reuse content buffer as output)
        gemm_nt<<<dim3(D_/128, SB_/128), 256>>>(attn, Wo + (size_t)l*D_*D_, nullptr, content,
                                                SB_, D_, D_, 0);
        // ln1: out1 = LN(h + proj)
        ln_kernel<<<SB_, 256>>>(h, content, ln1g + l*D_, ln1b + l*D_, out1);
        // ff1 = relu(out1 @ W1^T + b1)  (4096 x 3072 x 768)
        gemm_nt<<<dim3(DI_/128, SB_/128), 256>>>(out1, ffW1 + (size_t)l*DI_*D_, ffb1 + l*DI_,
                                                 ff, SB_, DI_, D_, 1);
        // ff2 = ff1 @ W2^T + b2         (4096 x 768 x 3072) -> reuse content
        gemm_nt<<<dim3(D_/128, SB_/128), 256>>>(ff, ffW2 + (size_t)l*D_*DI_, ffb2 + l*D_,
                                                content, SB_, D_, DI_, 2);
        // ln2: h = LN(out1 + ff2)
        ln_kernel<<<SB_, 256>>>(out1, content, ln2g + l*D_, ln2b + l*D_, h);
    }

    cudaMemcpyAsync(outH, h, (size_t)SB_*D_*sizeof(float),
                    cudaMemcpyDeviceToDevice);
}

// round 4
// speedup vs baseline: 2.9348x; 2.5779x over previous
#include <cuda_runtime.h>
#include <cuda_bf16.h>
#include <math.h>
#include <stdint.h>

// Problem dims
#define S_  1024
#define B_  4
#define D_  768
#define NH_ 12
#define DH_ 64
#define L_  4
#define DI_ 3072
#define SB_ (S_*B_)

// ---------------- scratch (device globals; no allocation allowed) ------------
__device__ float g_h[SB_*D_];
__device__ float g_q[SB_*D_];
__device__ float g_kv[SB_*2*D_];
__device__ float g_attn[SB_*D_];
__device__ float g_content[SB_*D_];
__device__ float g_cK[SB_*D_];
__device__ float g_diff[SB_*D_];
__device__ float g_ff[SB_*DI_];
__device__ float g_out1[SB_*D_];

// pack two floats into bf16x2 (lo = first arg)
__device__ __forceinline__ uint32_t pack_bf2(float a, float b) {
    __nv_bfloat162 h = __floats2bfloat162_rn(a, b);
    return *(uint32_t*)&h;
}

// ---------------- embedding + sinusoidal positional encoding -----------------
__global__ void embed_kernel(const int* __restrict__ inp,
                             const float* __restrict__ we,
                             float* __restrict__ h)
{
    int row = blockIdx.x;          // row = s*B + b
    int s = row / B_;
    int b = row % B_;
    int t = threadIdx.x;           // 256
    int tok = inp[s*B_ + b];
    float pos = (float)(S_ - 1 - s);
    const float lg = logf(10000.0f);
    for (int d = t; d < D_; d += 256) {
        int i = (d < 384) ? d : d - 384;
        float freq = expf(-((float)(2*i) / (float)D_) * lg);
        float ang = pos * freq;
        float pe = (d < 384) ? sinf(ang) : cosf(ang);
        h[(size_t)row*D_ + d] = we[(size_t)tok*D_ + d] * 27.712812921102035f + pe;
    }
}

// ---------------- NT GEMM (bf16 tensor cores, hi/lo split = ~fp32) -----------
// C[M,N] = A[M,K] @ B[N,K]^T.  128x128 block tile, KT=16, 256 threads (8 warps),
// warp tile 64x32 via m16n8k16 bf16 mma; per operand split x = hi + lo (bf16),
// accumulate hi*hi + hi*lo + lo*hi in fp32.  Double-buffered SMEM.
// SMEM row layout (20 words): words 0..7 = hi packed bf16x2 (k pairs),
// words 8..15 = lo packed, words 16..19 pad (keeps fragment LDS conflict-free).
// epi: 0 = none, 1 = bias+relu, 2 = bias
#define KT 16
#define KP 20
__global__ __launch_bounds__(256) void gemm_bf16s(
    const float* __restrict__ A, const float* __restrict__ Bm,
    const float* __restrict__ bias, float* __restrict__ C,
    int M, int N, int K, int epi)
{
    __shared__ __align__(16) uint32_t As[2][128][KP];
    __shared__ __align__(16) uint32_t Bs[2][128][KP];
    int tid  = threadIdx.x;
    int m0 = blockIdx.y * 128, n0 = blockIdx.x * 128;
    int warp = tid >> 5, lane = tid & 31;
    int wm = warp >> 2, wn = warp & 3;        // 2 x 4 warp grid
    int r0 = lane >> 2, cq = lane & 3;

    int lr = tid >> 2;          // 0..63
    int lc = (tid & 3) * 4;     // 0,4,8,12 (k offset in floats)
    int wc = lc >> 1;           // word col: 0,2,4,6
    const float* Ap = A  + (size_t)(m0 + lr)*K + lc;
    const float* Bp = Bm + (size_t)(n0 + lr)*K + lc;

    float acc[16][4];
    #pragma unroll
    for (int i = 0; i < 16; i++)
        #pragma unroll
        for (int j = 0; j < 4; j++) acc[i][j] = 0.f;

    // helper macro: split float4 into hi/lo packed words and store to smem row
    #define STORE_SPLIT(dst, row, vec)                                          \
    {                                                                           \
        float4 _v = (vec);                                                      \
        float hx = __bfloat162float(__float2bfloat16_rn(_v.x));                 \
        float hy = __bfloat162float(__float2bfloat16_rn(_v.y));                 \
        float hz = __bfloat162float(__float2bfloat16_rn(_v.z));                 \
        float hw = __bfloat162float(__float2bfloat16_rn(_v.w));                 \
        dst[row][wc+0] = pack_bf2(hx, hy);                                      \
        dst[row][wc+1] = pack_bf2(hz, hw);                                      \
        dst[row][8+wc+0] = pack_bf2(_v.x - hx, _v.y - hy);                      \
        dst[row][8+wc+1] = pack_bf2(_v.z - hz, _v.w - hw);                      \
    }

    // prologue: tile 0
    {
        float4 a0v = *(const float4*)Ap;
        float4 a1v = *(const float4*)(Ap + (size_t)64*K);
        float4 b0v = *(const float4*)Bp;
        float4 b1v = *(const float4*)(Bp + (size_t)64*K);
        STORE_SPLIT(As[0], lr,      a0v);
        STORE_SPLIT(As[0], lr + 64, a1v);
        STORE_SPLIT(Bs[0], lr,      b0v);
        STORE_SPLIT(Bs[0], lr + 64, b1v);
    }
    __syncthreads();

    int buf = 0;
    for (int k0 = KT; k0 < K + KT; k0 += KT) {
        bool more = (k0 < K);
        float4 a0v, a1v, b0v, b1v;
        if (more) {
            a0v = *(const float4*)(Ap + k0);
            a1v = *(const float4*)(Ap + (size_t)64*K + k0);
            b0v = *(const float4*)(Bp + k0);
            b1v = *(const float4*)(Bp + (size_t)64*K + k0);
        }
        // fragments: hi and lo for A (4 m-tiles) and B (4 n-tiles)
        uint32_t ah[4][4], al[4][4], bh[4][2], bl[4][2];
        #pragma unroll
        for (int mi = 0; mi < 4; mi++) {
            int mr = wm*64 + mi*16 + r0;
            ah[mi][0] = As[buf][mr    ][cq];
            ah[mi][1] = As[buf][mr + 8][cq];
            ah[mi][2] = As[buf][mr    ][cq + 4];
            ah[mi][3] = As[buf][mr + 8][cq + 4];
            al[mi][0] = As[buf][mr    ][8 + cq];
            al[mi][1] = As[buf][mr + 8][8 + cq];
            al[mi][2] = As[buf][mr    ][8 + cq + 4];
            al[mi][3] = As[buf][mr + 8][8 + cq + 4];
        }
        #pragma unroll
        for (int ni = 0; ni < 4; ni++) {
            int nr = wn*32 + ni*8 + r0;
            bh[ni][0] = Bs[buf][nr][cq];
            bh[ni][1] = Bs[buf][nr][cq + 4];
            bl[ni][0] = Bs[buf][nr][8 + cq];
            bl[ni][1] = Bs[buf][nr][8 + cq + 4];
        }
        #define MMA(d, a, bvec)                                                 \
            asm volatile(                                                        \
                "mma.sync.aligned.m16n8k16.row.col.f32.bf16.bf16.f32 "          \
                "{%0,%1,%2,%3}, {%4,%5,%6,%7}, {%8,%9}, {%0,%1,%2,%3};"        \
                : "+f"(d[0]), "+f"(d[1]), "+f"(d[2]), "+f"(d[3])                \
                : "r"(a[0]), "r"(a[1]), "r"(a[2]), "r"(a[3]),                   \
                  "r"(bvec[0]), "r"(bvec[1]))
        #pragma unroll
        for (int mi = 0; mi < 4; mi++)
            #pragma unroll
            for (int ni = 0; ni < 4; ni++) {
                float* d = acc[mi*4 + ni];
                MMA(d, ah[mi], bh[ni]);   // hi * hi
                MMA(d, ah[mi], bl[ni]);   // hi * lo
                MMA(d, al[mi], bh[ni]);   // lo * hi
            }
        #undef MMA
        if (more) {
            int nb = buf ^ 1;
            STORE_SPLIT(As[nb], lr,      a0v);
            STORE_SPLIT(As[nb], lr + 64, a1v);
            STORE_SPLIT(Bs[nb], lr,      b0v);
            STORE_SPLIT(Bs[nb], lr + 64, b1v);
            __syncthreads();
            buf = nb;
        }
    }
    #undef STORE_SPLIT

    // epilogue (c0,c1: row=r0, cols 2cq,2cq+1; c2,c3: row+8)
    #pragma unroll
    for (int mi = 0; mi < 4; mi++) {
        int m = m0 + wm*64 + mi*16 + r0;
        #pragma unroll
        for (int ni = 0; ni < 4; ni++) {
            int n = n0 + wn*32 + ni*8 + 2*cq;
            float* d = acc[mi*4 + ni];
            float2 v0 = {d[0], d[1]};
            float2 v1 = {d[2], d[3]};
            if (epi == 1) {
                float b0v = bias[n], b1v = bias[n+1];
                v0.x = fmaxf(v0.x + b0v, 0.f); v0.y = fmaxf(v0.y + b1v, 0.f);
                v1.x = fmaxf(v1.x + b0v, 0.f); v1.y = fmaxf(v1.y + b1v, 0.f);
            } else if (epi == 2) {
                float b0v = bias[n], b1v = bias[n+1];
                v0.x += b0v; v0.y += b1v;
                v1.x += b0v; v1.y += b1v;
            }
            *(float2*)(C + (size_t)m*N + n)       = v0;
            *(float2*)(C + (size_t)(m+8)*N + n)   = v1;
        }
    }
}

// ---------------- causal attention: 4 queries per block -----------------------
// pass-1 loop is warp-uniform (jb) so the sync-shuffles are always convergent.
__global__ __launch_bounds__(128) void attn_kernel(
    const float* __restrict__ q, const float* __restrict__ k,
    const float* __restrict__ v, float* __restrict__ o,
    int qS, int kvS, int oS)
{
    int iq0 = blockIdx.x * 4;
    int bn = blockIdx.y;
    int b = bn / NH_, n = bn % NH_;
    int col = n * DH_;
    int t = threadIdx.x, lane = t & 31, warp = t >> 5;
    int imax = iq0 + 3;

    __shared__ float sc[4][S_];
    __shared__ float wred[4][4];
    __shared__ float mxs[4], invs[4];
    __shared__ float avred[4][128];

    // q into registers: each lane holds 16 dims of each of the 4 queries
    int dq = (lane & 3) * 16;
    float4 qreg[4][4];
    #pragma unroll
    for (int qq = 0; qq < 4; qq++) {
        const float4* qp = (const float4*)(q + (size_t)((iq0+qq)*B_ + b)*qS + col + dq);
        #pragma unroll
        for (int c = 0; c < 4; c++) qreg[qq][c] = qp[c];
    }

    int myq = lane & 3;
    int r8  = lane >> 2;             // 0..7
    float lmax = -3.4e38f;
    for (int jb = warp*8; jb <= imax; jb += 32) {   // warp-uniform bound
        int j  = jb + r8;
        int jc = j <= imax ? j : imax;               // clamp for safe load
        const float4* kr = (const float4*)(k + (size_t)(jc*B_ + b)*kvS + col + dq);
        float dot[4] = {0.f, 0.f, 0.f, 0.f};
        #pragma unroll
        for (int c = 0; c < 4; c++) {
            float4 kv4 = kr[c];
            #pragma unroll
            for (int qq = 0; qq < 4; qq++) {
                float4 qv = qreg[qq][c];
                dot[qq] += kv4.x*qv.x + kv4.y*qv.y + kv4.z*qv.z + kv4.w*qv.w;
            }
        }
        #pragma unroll
        for (int qq = 0; qq < 4; qq++) {
            dot[qq] += __shfl_xor_sync(0xffffffff, dot[qq], 1);
            dot[qq] += __shfl_xor_sync(0xffffffff, dot[qq], 2);
        }
        float d = dot[myq] * 0.125f;                 // 1/sqrt(64)
        bool valid = (j <= iq0 + myq);
        d = valid ? d : -3.4e38f;
        if (j <= imax) { sc[myq][j] = d; lmax = fmaxf(lmax, d); }
    }
    // reduce lmax across lanes with same myq (stride-4 groups)
    lmax = fmaxf(lmax, __shfl_xor_sync(0xffffffff, lmax, 4));
    lmax = fmaxf(lmax, __shfl_xor_sync(0xffffffff, lmax, 8));
    lmax = fmaxf(lmax, __shfl_xor_sync(0xffffffff, lmax, 16));
    if (lane < 4) wred[warp][lane] = lmax;
    __syncthreads();
    if (t < 4) {
        float m = fmaxf(fmaxf(wred[0][t], wred[1][t]), fmaxf(wred[2][t], wred[3][t]));
        mxs[t] = m;
    }
    __syncthreads();

    // pass 2: exp + sum (warp w handles query w)
    {
        int qq = warp;
        float mx = mxs[qq];
        float lsum = 0.f;
        for (int j = lane; j <= imax; j += 32) {
            float e = expf(sc[qq][j] - mx);
            sc[qq][j] = e;
            lsum += e;
        }
        #pragma unroll
        for (int off = 16; off > 0; off >>= 1)
            lsum += __shfl_xor_sync(0xffffffff, lsum, off);
        if (lane == 0) invs[qq] = 1.f / lsum;
    }
    __syncthreads();

    // pass 3: AV
    int d = t & 63, half = t >> 6;
    float acc[4] = {0.f, 0.f, 0.f, 0.f};
    for (int j = half; j <= imax; j += 2) {
        float vv = v[(size_t)(j*B_ + b)*kvS + col + d];
        #pragma unroll
        for (int qq = 0; qq < 4; qq++) acc[qq] += sc[qq][j] * vv;
    }
    #pragma unroll
    for (int qq = 0; qq < 4; qq++) avred[qq][t] = acc[qq];
    __syncthreads();
    #pragma unroll
    for (int g = 0; g < 2; g++) {
        int qq = (t >> 6) + g*2;
        o[(size_t)((iq0+qq)*B_ + b)*oS + col + d] =
            (avred[qq][d] + avred[qq][d + 64]) * invs[qq];
    }
}

// -------- memory retrieval + delta + fused gated combine ----------------------
__global__ __launch_bounds__(256) void mem_retrieve(
    const float* __restrict__ q, const float* __restrict__ kp,
    const float* __restrict__ vp, const float* __restrict__ memory,
    const float* __restrict__ mem_norm, int l,
    const float* __restrict__ attn, float gate,
    float* __restrict__ content, float* __restrict__ diff, float* __restrict__ cKout,
    int qS, int kvS)
{
    int bn = blockIdx.x;
    int b = bn / NH_, n = bn % NH_;
    int chunk = blockIdx.y;          // 8 chunks of 128 s-values
    int t = threadIdx.x;

    __shared__ float Msh[DH_][DH_+1];
    __shared__ float normsh[DH_];
    __shared__ float cqsh[4][DH_];
    __shared__ float cksh[4][DH_];

    const float* Mg = memory + ((size_t)(l*B_ + b)*NH_ + n)*DH_*DH_;
    for (int idx = t; idx < DH_*DH_; idx += 256) Msh[idx >> 6][idx & 63] = Mg[idx];
    if (t < DH_) normsh[t] = mem_norm[((size_t)(l*B_ + b)*NH_ + n)*DH_ + t];
    __syncthreads();

    int g = t >> 6, d = t & 63;
    int col = n * DH_;
    for (int it = 0; it < 32; ++it) {
        int s = chunk*128 + it*4 + g;
        size_t row = (size_t)(s*B_ + b);
        float qv = q [row*qS  + col + d];
        float vv = vp[row*kvS + col + d];
        float cq = qv > 0.f ? qv + 1.f : expf(qv);
        float ck = vv > 0.f ? vv + 1.f : expf(vv);
        cqsh[g][d] = cq; cksh[g][d] = ck;
        __syncthreads();
        float accA = 0.f, accB = 0.f, denQ = 0.f, denK = 0.f;
        #pragma unroll 8
        for (int kk = 0; kk < DH_; kk++) {
            float mq = Msh[kk][d];
            accA += cqsh[g][kk] * mq;
            accB += cksh[g][kk] * mq;
            denQ += cqsh[g][kk] * normsh[kk];
            denK += cksh[g][kk] * normsh[kk];
        }
        size_t oidx = row*D_ + col + d;
        content[oidx] = gate * (accA / denQ) + (1.f - gate) * attn[oidx];
        diff[oidx]    = kp[row*kvS + col + d] - accB / denK;
        cKout[oidx]   = ck;
        __syncthreads();
    }
}

// -------- memory update: newM[k][v] = M[k][v] + sum_s cK[s,k]*diff[s,v] ------
__global__ __launch_bounds__(256) void mem_update(
    const float* __restrict__ cK, const float* __restrict__ diff,
    const float* __restrict__ memory, int l, float* __restrict__ outM)
{
    int bn = blockIdx.x;
    int b = bn / NH_, n = bn % NH_;
    __shared__ float aS[16][DH_];
    __shared__ float bS[16][DH_];
    int t = threadIdx.x;
    int tx = t & 15, ty = t >> 4;
    float acc[4][4] = {};
    int col = n * DH_;
    int r  = t >> 4;
    int c4 = (t & 15) * 4;
    for (int s0 = 0; s0 < S_; s0 += 16) {
        size_t row = (size_t)((s0 + r)*B_ + b);
        *(float4*)&aS[r][c4] = *(const float4*)(cK   + row*D_ + col + c4);
        *(float4*)&bS[r][c4] = *(const float4*)(diff + row*D_ + col + c4);
        __syncthreads();
        #pragma unroll
        for (int ss = 0; ss < 16; ss++) {
            float a[4], bb[4];
            #pragma unroll
            for (int u = 0; u < 4; u++) { a[u] = aS[ss][ty*4+u]; bb[u] = bS[ss][tx*4+u]; }
            #pragma unroll
            for (int i = 0; i < 4; i++)
                #pragma unroll
                for (int j = 0; j < 4; j++)
                    acc[i][j] = fmaf(a[i], bb[j], acc[i][j]);
        }
        __syncthreads();
    }
    const float* Mg = memory + ((size_t)(l*B_ + b)*NH_ + n)*DH_*DH_;
    float*       Og = outM   + ((size_t)(l*B_ + b)*NH_ + n)*DH_*DH_;
    #pragma unroll
    for (int i = 0; i < 4; i++)
        #pragma unroll
        for (int j = 0; j < 4; j++) {
            int kk = ty*4 + i, vv = tx*4 + j;
            Og[kk*DH_ + vv] = Mg[kk*DH_ + vv] + acc[i][j];
        }
}

// -------- norm update: outN = mem_norm + sum_s cK (parallel over s) ----------
__global__ __launch_bounds__(512) void norm_update(
    const float* __restrict__ cK, const float* __restrict__ mem_norm, int l,
    float* __restrict__ outN)
{
    int bn = blockIdx.x;
    int b = bn / NH_, n = bn % NH_;
    int t = threadIdx.x;
    int d = t & 63, sg = t >> 6;   // 8 s-groups
    int col = n * DH_;
    float acc = 0.f;
    for (int s = sg; s < S_; s += 8)
        acc += cK[(size_t)(s*B_ + b)*D_ + col + d];
    __shared__ float red[512];
    red[t] = acc; __syncthreads();
    if (t < 256) red[t] += red[t + 256]; __syncthreads();
    if (t < 128) red[t] += red[t + 128]; __syncthreads();
    if (t < 64) {
        size_t o = ((size_t)(l*B_ + b)*NH_ + n)*DH_ + t;
        outN[o] = mem_norm[o] + red[t] + red[t + 64];
    }
}

// -------- layernorm with residual: out = LN(res + y) --------------------------
__global__ __launch_bounds__(256) void ln_kernel(
    const float* __restrict__ res, const float* __restrict__ y,
    const float* __restrict__ g, const float* __restrict__ bb,
    float* __restrict__ out)
{
    int row = blockIdx.x;
    int t = threadIdx.x;
    __shared__ float red[256];
    size_t base = (size_t)row * D_;
    float x0 = res[base + t      ] + y[base + t      ];
    float x1 = res[base + t + 256] + y[base + t + 256];
    float x2 = res[base + t + 512] + y[base + t + 512];
    red[t] = x0 + x1 + x2; __syncthreads();
    for (int o = 128; o > 0; o >>= 1) { if (t < o) red[t] += red[t+o]; __syncthreads(); }
    float mu = red[0] * (1.f / 768.f); __syncthreads();
    float d0 = x0 - mu, d1 = x1 - mu, d2 = x2 - mu;
    red[t] = d0*d0 + d1*d1 + d2*d2; __syncthreads();
    for (int o = 128; o > 0; o >>= 1) { if (t < o) red[t] += red[t+o]; __syncthreads(); }
    float inv = rsqrtf(red[0] * (1.f / 768.f) + 1e-5f);
    out[base + t      ] = d0 * inv * g[t      ] + bb[t      ];
    out[base + t + 256] = d1 * inv * g[t + 256] + bb[t + 256];
    out[base + t + 512] = d2 * inv * g[t + 512] + bb[t + 512];
}

// ------------------------------- launcher -------------------------------------
extern "C" void kernel_launch(void* const* d_in, const int* in_sizes, int n_in,
                              void* d_out, int out_size)
{
    const int*   inp      = (const int*)  d_in[0];
    const float* word_emb = (const float*)d_in[1];
    const float* Wq       = (const float*)d_in[2];
    const float* Wkv      = (const float*)d_in[3];
    const float* Wo       = (const float*)d_in[4];
    const float* ln1g     = (const float*)d_in[5];
    const float* ln1b     = (const float*)d_in[6];
    const float* ffW1     = (const float*)d_in[7];
    const float* ffb1     = (const float*)d_in[8];
    const float* ffW2     = (const float*)d_in[9];
    const float* ffb2     = (const float*)d_in[10];
    const float* ln2g     = (const float*)d_in[11];
    const float* ln2b     = (const float*)d_in[12];
    const float* memory   = (const float*)d_in[13];
    const float* mem_norm = (const float*)d_in[14];

    float* out  = (float*)d_out;
    float* outH = out;                         // (S,B,D)
    float* outM = out + (size_t)SB_*D_;        // (L,B,NH,DH,DH)
    float* outN = outM + (size_t)L_*B_*NH_*DH_*DH_;  // (L,B,NH,DH)

    float *h, *q, *kv, *attn, *content, *cK, *diff, *ff, *out1;
    cudaGetSymbolAddress((void**)&h,       g_h);
    cudaGetSymbolAddress((void**)&q,       g_q);
    cudaGetSymbolAddress((void**)&kv,      g_kv);
    cudaGetSymbolAddress((void**)&attn,    g_attn);
    cudaGetSymbolAddress((void**)&content, g_content);
    cudaGetSymbolAddress((void**)&cK,      g_cK);
    cudaGetSymbolAddress((void**)&diff,    g_diff);
    cudaGetSymbolAddress((void**)&ff,      g_ff);
    cudaGetSymbolAddress((void**)&out1,    g_out1);

    const float gate = 1.0f / (1.0f + expf(-0.01f));

    embed_kernel<<<SB_, 256>>>(inp, word_emb, h);

    for (int l = 0; l < L_; l++) {
        // q = h @ Wq^T   (4096 x 768 x 768)
        gemm_bf16s<<<dim3(D_/128, SB_/128), 256>>>(h, Wq + (size_t)l*D_*D_, nullptr, q,
                                                   SB_, D_, D_, 0);
        // kv = h @ Wkv^T (4096 x 1536 x 768)
        gemm_bf16s<<<dim3(2*D_/128, SB_/128), 256>>>(h, Wkv + (size_t)l*2*D_*D_, nullptr, kv,
                                                     SB_, 2*D_, D_, 0);
        // local causal attention (4 queries per block)
        attn_kernel<<<dim3(S_/4, B_*NH_), 128>>>(q, kv /*k*/, kv + D_ /*v*/, attn,
                                                 D_, 2*D_, D_);
        // memory retrieval + delta + fused gated combine (content = gated mix)
        mem_retrieve<<<dim3(B_*NH_, 8), 256>>>(q, kv /*k*/, kv + D_ /*v*/,
                                               memory, mem_norm, l,
                                               attn, gate,
                                               content, diff, cK, D_, 2*D_);
        // memory + norm updates straight into d_out
        mem_update<<<B_*NH_, 256>>>(cK, diff, memory, l, outM);
        norm_update<<<B_*NH_, 512>>>(cK, mem_norm, l, outN);
        // Wo projection (content holds the gated attention mix; write into attn)
        gemm_bf16s<<<dim3(D_/128, SB_/128), 256>>>(content, Wo + (size_t)l*D_*D_, nullptr, attn,
                                                   SB_, D_, D_, 0);
        // ln1: out1 = LN(h + proj)
        ln_kernel<<<SB_, 256>>>(h, attn, ln1g + l*D_, ln1b + l*D_, out1);
        // ff1 = relu(out1 @ W1^T + b1)  (4096 x 3072 x 768)
        gemm_bf16s<<<dim3(DI_/128, SB_/128), 256>>>(out1, ffW1 + (size_t)l*DI_*D_, ffb1 + l*DI_,
                                                    ff, SB_, DI_, D_, 1);
        // ff2 = ff1 @ W2^T + b2         (4096 x 768 x 3072)
        gemm_bf16s<<<dim3(D_/128, SB_/128), 256>>>(ff, ffW2 + (size_t)l*D_*DI_, ffb2 + l*D_,
                                                   content, SB_, D_, DI_, 2);
        // ln2: h = LN(out1 + ff2)
        ln_kernel<<<SB_, 256>>>(out1, content, ln2g + l*D_, ln2b + l*D_, h);
    }

    cudaMemcpyAsync(outH, h, (size_t)SB_*D_*sizeof(float),
                    cudaMemcpyDeviceToDevice);
}

// round 5
// speedup vs baseline: 3.1226x; 1.0640x over previous
#include <cuda_runtime.h>
#include <cuda_bf16.h>
#include <math.h>
#include <stdint.h>

// Problem dims
#define S_  1024
#define B_  4
#define D_  768
#define NH_ 12
#define DH_ 64
#define L_  4
#define DI_ 3072
#define SB_ (S_*B_)

// ---------------- scratch (device globals; no allocation allowed) ------------
__device__ float g_h[SB_*D_];
__device__ float g_q[SB_*D_];
__device__ float g_kv[SB_*2*D_];
__device__ float g_attn[SB_*D_];
__device__ float g_content[SB_*D_];
__device__ float g_cK[SB_*D_];
__device__ float g_diff[SB_*D_];
__device__ float g_ff[SB_*DI_];
__device__ float g_out1[SB_*D_];

// pack two floats into bf16x2 (lo = first arg)
__device__ __forceinline__ uint32_t pack_bf2(float a, float b) {
    __nv_bfloat162 h = __floats2bfloat162_rn(a, b);
    return *(uint32_t*)&h;
}

// ---------------- embedding + sinusoidal positional encoding -----------------
__global__ void embed_kernel(const int* __restrict__ inp,
                             const float* __restrict__ we,
                             float* __restrict__ h)
{
    int row = blockIdx.x;          // row = s*B + b
    int s = row / B_;
    int b = row % B_;
    int t = threadIdx.x;           // 256
    int tok = inp[s*B_ + b];
    float pos = (float)(S_ - 1 - s);
    const float lg = logf(10000.0f);
    for (int d = t; d < D_; d += 256) {
        int i = (d < 384) ? d : d - 384;
        float freq = expf(-((float)(2*i) / (float)D_) * lg);
        float ang = pos * freq;
        float pe = (d < 384) ? sinf(ang) : cosf(ang);
        h[(size_t)row*D_ + d] = we[(size_t)tok*D_ + d] * 27.712812921102035f + pe;
    }
}

// ---------------- NT GEMM (bf16 tensor cores, hi/lo split = ~fp32) -----------
#define KT 16
#define KP 20
__global__ __launch_bounds__(256) void gemm_bf16s(
    const float* __restrict__ A, const float* __restrict__ Bm,
    const float* __restrict__ bias, float* __restrict__ C,
    int M, int N, int K, int epi)
{
    __shared__ __align__(16) uint32_t As[2][128][KP];
    __shared__ __align__(16) uint32_t Bs[2][128][KP];
    int tid  = threadIdx.x;
    int m0 = blockIdx.y * 128, n0 = blockIdx.x * 128;
    int warp = tid >> 5, lane = tid & 31;
    int wm = warp >> 2, wn = warp & 3;        // 2 x 4 warp grid
    int r0 = lane >> 2, cq = lane & 3;

    int lr = tid >> 2;          // 0..63
    int lc = (tid & 3) * 4;     // 0,4,8,12 (k offset in floats)
    int wc = lc >> 1;           // word col: 0,2,4,6
    const float* Ap = A  + (size_t)(m0 + lr)*K + lc;
    const float* Bp = Bm + (size_t)(n0 + lr)*K + lc;

    float acc[16][4];
    #pragma unroll
    for (int i = 0; i < 16; i++)
        #pragma unroll
        for (int j = 0; j < 4; j++) acc[i][j] = 0.f;

    #define STORE_SPLIT(dst, row, vec)                                          \
    {                                                                           \
        float4 _v = (vec);                                                      \
        float hx = __bfloat162float(__float2bfloat16_rn(_v.x));                 \
        float hy = __bfloat162float(__float2bfloat16_rn(_v.y));                 \
        float hz = __bfloat162float(__float2bfloat16_rn(_v.z));                 \
        float hw = __bfloat162float(__float2bfloat16_rn(_v.w));                 \
        dst[row][wc+0] = pack_bf2(hx, hy);                                      \
        dst[row][wc+1] = pack_bf2(hz, hw);                                      \
        dst[row][8+wc+0] = pack_bf2(_v.x - hx, _v.y - hy);                      \
        dst[row][8+wc+1] = pack_bf2(_v.z - hz, _v.w - hw);                      \
    }

    {
        float4 a0v = *(const float4*)Ap;
        float4 a1v = *(const float4*)(Ap + (size_t)64*K);
        float4 b0v = *(const float4*)Bp;
        float4 b1v = *(const float4*)(Bp + (size_t)64*K);
        STORE_SPLIT(As[0], lr,      a0v);
        STORE_SPLIT(As[0], lr + 64, a1v);
        STORE_SPLIT(Bs[0], lr,      b0v);
        STORE_SPLIT(Bs[0], lr + 64, b1v);
    }
    __syncthreads();

    int buf = 0;
    for (int k0 = KT; k0 < K + KT; k0 += KT) {
        bool more = (k0 < K);
        float4 a0v, a1v, b0v, b1v;
        if (more) {
            a0v = *(const float4*)(Ap + k0);
            a1v = *(const float4*)(Ap + (size_t)64*K + k0);
            b0v = *(const float4*)(Bp + k0);
            b1v = *(const float4*)(Bp + (size_t)64*K + k0);
        }
        uint32_t ah[4][4], al[4][4], bh[4][2], bl[4][2];
        #pragma unroll
        for (int mi = 0; mi < 4; mi++) {
            int mr = wm*64 + mi*16 + r0;
            ah[mi][0] = As[buf][mr    ][cq];
            ah[mi][1] = As[buf][mr + 8][cq];
            ah[mi][2] = As[buf][mr    ][cq + 4];
            ah[mi][3] = As[buf][mr + 8][cq + 4];
            al[mi][0] = As[buf][mr    ][8 + cq];
            al[mi][1] = As[buf][mr + 8][8 + cq];
            al[mi][2] = As[buf][mr    ][8 + cq + 4];
            al[mi][3] = As[buf][mr + 8][8 + cq + 4];
        }
        #pragma unroll
        for (int ni = 0; ni < 4; ni++) {
            int nr = wn*32 + ni*8 + r0;
            bh[ni][0] = Bs[buf][nr][cq];
            bh[ni][1] = Bs[buf][nr][cq + 4];
            bl[ni][0] = Bs[buf][nr][8 + cq];
            bl[ni][1] = Bs[buf][nr][8 + cq + 4];
        }
        #define MMA(d, a, bvec)                                                 \
            asm volatile(                                                        \
                "mma.sync.aligned.m16n8k16.row.col.f32.bf16.bf16.f32 "          \
                "{%0,%1,%2,%3}, {%4,%5,%6,%7}, {%8,%9}, {%0,%1,%2,%3};"        \
                : "+f"(d[0]), "+f"(d[1]), "+f"(d[2]), "+f"(d[3])                \
                : "r"(a[0]), "r"(a[1]), "r"(a[2]), "r"(a[3]),                   \
                  "r"(bvec[0]), "r"(bvec[1]))
        #pragma unroll
        for (int mi = 0; mi < 4; mi++)
            #pragma unroll
            for (int ni = 0; ni < 4; ni++) {
                float* d = acc[mi*4 + ni];
                MMA(d, ah[mi], bh[ni]);   // hi * hi
                MMA(d, ah[mi], bl[ni]);   // hi * lo
                MMA(d, al[mi], bh[ni]);   // lo * hi
            }
        #undef MMA
        if (more) {
            int nb = buf ^ 1;
            STORE_SPLIT(As[nb], lr,      a0v);
            STORE_SPLIT(As[nb], lr + 64, a1v);
            STORE_SPLIT(Bs[nb], lr,      b0v);
            STORE_SPLIT(Bs[nb], lr + 64, b1v);
            __syncthreads();
            buf = nb;
        }
    }
    #undef STORE_SPLIT

    #pragma unroll
    for (int mi = 0; mi < 4; mi++) {
        int m = m0 + wm*64 + mi*16 + r0;
        #pragma unroll
        for (int ni = 0; ni < 4; ni++) {
            int n = n0 + wn*32 + ni*8 + 2*cq;
            float* d = acc[mi*4 + ni];
            float2 v0 = {d[0], d[1]};
            float2 v1 = {d[2], d[3]};
            if (epi == 1) {
                float b0v = bias[n], b1v = bias[n+1];
                v0.x = fmaxf(v0.x + b0v, 0.f); v0.y = fmaxf(v0.y + b1v, 0.f);
                v1.x = fmaxf(v1.x + b0v, 0.f); v1.y = fmaxf(v1.y + b1v, 0.f);
            } else if (epi == 2) {
                float b0v = bias[n], b1v = bias[n+1];
                v0.x += b0v; v0.y += b1v;
                v1.x += b0v; v1.y += b1v;
            }
            *(float2*)(C + (size_t)m*N + n)       = v0;
            *(float2*)(C + (size_t)(m+8)*N + n)   = v1;
        }
    }
}

// ---------------- causal attention: 16 queries per block ----------------------
// 256 threads. Pass 1: 16-lane groups each own one K row per step; every lane
// holds 4 dims of all 16 queries; butterfly tree-reduce (15 shuffles) leaves
// lane (lane&15) with the dot for query (lane&15). 4 FMA per K byte.
#define QB 16
#define SCP (S_ + 1)     // padded score row
__global__ __launch_bounds__(256, 2) void attn_flash(
    const float* __restrict__ q, const float* __restrict__ k,
    const float* __restrict__ v, float* __restrict__ o,
    int qS, int kvS, int oS)
{
    int iq0 = blockIdx.x * QB;
    int bn = blockIdx.y;
    int b = bn / NH_, n = bn % NH_;
    int col = n * DH_;
    int t = threadIdx.x, lane = t & 31, warp = t >> 5;
    int imax = iq0 + QB - 1;

    extern __shared__ float sm[];
    float* sc    = sm;                 // [QB][SCP]
    float* avred = sm + QB*SCP;        // [QB][256]
    __shared__ float wred[8][16];
    __shared__ float mxs[QB], invs[QB];

    // each lane: 4 dims (at dq) of all 16 queries
    int qidx = lane & 15;
    int dq = qidx * 4;
    float4 qv[QB];
    #pragma unroll
    for (int qq = 0; qq < QB; qq++)
        qv[qq] = *(const float4*)(q + (size_t)((iq0+qq)*B_ + b)*qS + col + dq);

    // ---- pass 1: scores + running max ----
    int g = warp*2 + (lane >> 4);      // 16 groups
    float lmax = -3.4e38f;
    for (int jb = 0; jb <= imax; jb += 16) {   // block-uniform bound
        int j  = jb + g;
        int jc = j <= imax ? j : imax;
        float4 kv4 = *(const float4*)(k + (size_t)(jc*B_ + b)*kvS + col + dq);
        float d[QB];
        #pragma unroll
        for (int qq = 0; qq < QB; qq++)
            d[qq] = kv4.x*qv[qq].x + kv4.y*qv[qq].y + kv4.z*qv[qq].z + kv4.w*qv[qq].w;
        // butterfly: after stage `off`, lane keeps cnt dots; final d[0] = dot(lane&15)
        #pragma unroll
        for (int off = 8; off >= 1; off >>= 1) {
            int cnt = off;
            bool hi = (lane & off) != 0;
            #pragma unroll
            for (int i = 0; i < 8; i++) {
                if (i >= cnt) break;
                float send = hi ? d[i] : d[i + cnt];
                float recv = __shfl_xor_sync(0xffffffff, send, off);
                d[i] = (hi ? d[i + cnt] : d[i]) + recv;
            }
        }
        float val = (j <= iq0 + qidx) ? d[0]*0.125f : -3.4e38f;
        if (j <= imax) {
            sc[qidx*SCP + j] = val;
            lmax = fmaxf(lmax, val);
        }
    }
    // combine two groups in each warp (same qidx at lane^16)
    lmax = fmaxf(lmax, __shfl_xor_sync(0xffffffff, lmax, 16));
    if (lane < 16) wred[warp][lane] = lmax;
    __syncthreads();
    if (t < QB) {
        float m = wred[0][t];
        #pragma unroll
        for (int w = 1; w < 8; w++) m = fmaxf(m, wred[w][t]);
        mxs[t] = m;
    }
    __syncthreads();

    // ---- pass 2: exp + sum (each warp: queries warp, warp+8) ----
    #pragma unroll
    for (int u = 0; u < 2; u++) {
        int qq = warp + u*8;
        float mx = mxs[qq];
        float* srow = sc + qq*SCP;
        float lsum = 0.f;
        for (int j = lane; j <= imax; j += 32) {
            float e = __expf(srow[j] - mx);   // masked entries -> exp(-huge)=0
            srow[j] = e;
            lsum += e;
        }
        #pragma unroll
        for (int off = 16; off > 0; off >>= 1)
            lsum += __shfl_xor_sync(0xffffffff, lsum, off);
        if (lane == 0) invs[qq] = 1.f / lsum;
    }
    __syncthreads();

    // ---- pass 3: AV (each V float feeds 16 FMAs) ----
    int d = t & 63, jg = t >> 6;      // 4 j-groups
    float acc[QB];
    #pragma unroll
    for (int qq = 0; qq < QB; qq++) acc[qq] = 0.f;
    for (int j = jg; j <= imax; j += 4) {
        float vv = v[(size_t)(j*B_ + b)*kvS + col + d];
        #pragma unroll
        for (int qq = 0; qq < QB; qq++)
            acc[qq] += sc[qq*SCP + j] * vv;
    }
    #pragma unroll
    for (int qq = 0; qq < QB; qq++) avred[qq*256 + t] = acc[qq];
    __syncthreads();
    int qh = t >> 6;                   // 0..3
    #pragma unroll
    for (int u = 0; u < 4; u++) {
        int qq = qh + u*4;
        float s = avred[qq*256 + d] + avred[qq*256 + 64 + d]
                + avred[qq*256 + 128 + d] + avred[qq*256 + 192 + d];
        o[(size_t)((iq0+qq)*B_ + b)*oS + col + d] = s * invs[qq];
    }
}

// -------- memory retrieval + delta + fused gated combine ----------------------
__global__ __launch_bounds__(256) void mem_retrieve(
    const float* __restrict__ q, const float* __restrict__ kp,
    const float* __restrict__ vp, const float* __restrict__ memory,
    const float* __restrict__ mem_norm, int l,
    const float* __restrict__ attn, float gate,
    float* __restrict__ content, float* __restrict__ diff, float* __restrict__ cKout,
    int qS, int kvS)
{
    int bn = blockIdx.x;
    int b = bn / NH_, n = bn % NH_;
    int chunk = blockIdx.y;          // 8 chunks of 128 s-values
    int t = threadIdx.x;

    __shared__ float Msh[DH_][DH_+1];
    __shared__ float normsh[DH_];
    __shared__ float cqsh[4][DH_];
    __shared__ float cksh[4][DH_];

    const float* Mg = memory + ((size_t)(l*B_ + b)*NH_ + n)*DH_*DH_;
    for (int idx = t; idx < DH_*DH_; idx += 256) Msh[idx >> 6][idx & 63] = Mg[idx];
    if (t < DH_) normsh[t] = mem_norm[((size_t)(l*B_ + b)*NH_ + n)*DH_ + t];
    __syncthreads();

    int g = t >> 6, d = t & 63;
    int col = n * DH_;
    for (int it = 0; it < 32; ++it) {
        int s = chunk*128 + it*4 + g;
        size_t row = (size_t)(s*B_ + b);
        float qvl = q [row*qS  + col + d];
        float vvl = vp[row*kvS + col + d];
        float cq = qvl > 0.f ? qvl + 1.f : __expf(qvl);
        float ck = vvl > 0.f ? vvl + 1.f : __expf(vvl);
        cqsh[g][d] = cq; cksh[g][d] = ck;
        __syncthreads();
        float accA = 0.f, accB = 0.f, denQ = 0.f, denK = 0.f;
        #pragma unroll 8
        for (int kk = 0; kk < DH_; kk++) {
            float mq = Msh[kk][d];
            accA += cqsh[g][kk] * mq;
            accB += cksh[g][kk] * mq;
            denQ += cqsh[g][kk] * normsh[kk];
            denK += cksh[g][kk] * normsh[kk];
        }
        size_t oidx = row*D_ + col + d;
        content[oidx] = gate * (accA / denQ) + (1.f - gate) * attn[oidx];
        diff[oidx]    = kp[row*kvS + col + d] - accB / denK;
        cKout[oidx]   = ck;
        __syncthreads();
    }
}

// -------- memory update: newM[k][v] = M[k][v] + sum_s cK[s,k]*diff[s,v] ------
__global__ __launch_bounds__(256) void mem_update(
    const float* __restrict__ cK, const float* __restrict__ diff,
    const float* __restrict__ memory, int l, float* __restrict__ outM)
{
    int bn = blockIdx.x;
    int b = bn / NH_, n = bn % NH_;
    __shared__ float aS[16][DH_];
    __shared__ float bS[16][DH_];
    int t = threadIdx.x;
    int tx = t & 15, ty = t >> 4;
    float acc[4][4] = {};
    int col = n * DH_;
    int r  = t >> 4;
    int c4 = (t & 15) * 4;
    for (int s0 = 0; s0 < S_; s0 += 16) {
        size_t row = (size_t)((s0 + r)*B_ + b);
        *(float4*)&aS[r][c4] = *(const float4*)(cK   + row*D_ + col + c4);
        *(float4*)&bS[r][c4] = *(const float4*)(diff + row*D_ + col + c4);
        __syncthreads();
        #pragma unroll
        for (int ss = 0; ss < 16; ss++) {
            float a[4], bb[4];
            #pragma unroll
            for (int u = 0; u < 4; u++) { a[u] = aS[ss][ty*4+u]; bb[u] = bS[ss][tx*4+u]; }
            #pragma unroll
            for (int i = 0; i < 4; i++)
                #pragma unroll
                for (int j = 0; j < 4; j++)
                    acc[i][j] = fmaf(a[i], bb[j], acc[i][j]);
        }
        __syncthreads();
    }
    const float* Mg = memory + ((size_t)(l*B_ + b)*NH_ + n)*DH_*DH_;
    float*       Og = outM   + ((size_t)(l*B_ + b)*NH_ + n)*DH_*DH_;
    #pragma unroll
    for (int i = 0; i < 4; i++)
        #pragma unroll
        for (int j = 0; j < 4; j++) {
            int kk = ty*4 + i, vv = tx*4 + j;
            Og[kk*DH_ + vv] = Mg[kk*DH_ + vv] + acc[i][j];
        }
}

// -------- norm update: outN = mem_norm + sum_s cK (parallel over s) ----------
__global__ __launch_bounds__(512) void norm_update(
    const float* __restrict__ cK, const float* __restrict__ mem_norm, int l,
    float* __restrict__ outN)
{
    int bn = blockIdx.x;
    int b = bn / NH_, n = bn % NH_;
    int t = threadIdx.x;
    int d = t & 63, sg = t >> 6;   // 8 s-groups
    int col = n * DH_;
    float acc = 0.f;
    for (int s = sg; s < S_; s += 8)
        acc += cK[(size_t)(s*B_ + b)*D_ + col + d];
    __shared__ float red[512];
    red[t] = acc; __syncthreads();
    if (t < 256) red[t] += red[t + 256]; __syncthreads();
    if (t < 128) red[t] += red[t + 128]; __syncthreads();
    if (t < 64) {
        size_t o = ((size_t)(l*B_ + b)*NH_ + n)*DH_ + t;
        outN[o] = mem_norm[o] + red[t] + red[t + 64];
    }
}

// -------- layernorm with residual: out = LN(res + y) --------------------------
__global__ __launch_bounds__(256) void ln_kernel(
    const float* __restrict__ res, const float* __restrict__ y,
    const float* __restrict__ g, const float* __restrict__ bb,
    float* __restrict__ out)
{
    int row = blockIdx.x;
    int t = threadIdx.x;
    __shared__ float red[256];
    size_t base = (size_t)row * D_;
    float x0 = res[base + t      ] + y[base + t      ];
    float x1 = res[base + t + 256] + y[base + t + 256];
    float x2 = res[base + t + 512] + y[base + t + 512];
    red[t] = x0 + x1 + x2; __syncthreads();
    for (int o = 128; o > 0; o >>= 1) { if (t < o) red[t] += red[t+o]; __syncthreads(); }
    float mu = red[0] * (1.f / 768.f); __syncthreads();
    float d0 = x0 - mu, d1 = x1 - mu, d2 = x2 - mu;
    red[t] = d0*d0 + d1*d1 + d2*d2; __syncthreads();
    for (int o = 128; o > 0; o >>= 1) { if (t < o) red[t] += red[t+o]; __syncthreads(); }
    float inv = rsqrtf(red[0] * (1.f / 768.f) + 1e-5f);
    out[base + t      ] = d0 * inv * g[t      ] + bb[t      ];
    out[base + t + 256] = d1 * inv * g[t + 256] + bb[t + 256];
    out[base + t + 512] = d2 * inv * g[t + 512] + bb[t + 512];
}

// ------------------------------- launcher -------------------------------------
extern "C" void kernel_launch(void* const* d_in, const int* in_sizes, int n_in,
                              void* d_out, int out_size)
{
    const int*   inp      = (const int*)  d_in[0];
    const float* word_emb = (const float*)d_in[1];
    const float* Wq       = (const float*)d_in[2];
    const float* Wkv      = (const float*)d_in[3];
    const float* Wo       = (const float*)d_in[4];
    const float* ln1g     = (const float*)d_in[5];
    const float* ln1b     = (const float*)d_in[6];
    const float* ffW1     = (const float*)d_in[7];
    const float* ffb1     = (const float*)d_in[8];
    const float* ffW2     = (const float*)d_in[9];
    const float* ffb2     = (const float*)d_in[10];
    const float* ln2g     = (const float*)d_in[11];
    const float* ln2b     = (const float*)d_in[12];
    const float* memory   = (const float*)d_in[13];
    const float* mem_norm = (const float*)d_in[14];

    float* out  = (float*)d_out;
    float* outH = out;                         // (S,B,D)
    float* outM = out + (size_t)SB_*D_;        // (L,B,NH,DH,DH)
    float* outN = outM + (size_t)L_*B_*NH_*DH_*DH_;  // (L,B,NH,DH)

    float *h, *q, *kv, *attn, *content, *cK, *diff, *ff, *out1;
    cudaGetSymbolAddress((void**)&h,       g_h);
    cudaGetSymbolAddress((void**)&q,       g_q);
    cudaGetSymbolAddress((void**)&kv,      g_kv);
    cudaGetSymbolAddress((void**)&attn,    g_attn);
    cudaGetSymbolAddress((void**)&content, g_content);
    cudaGetSymbolAddress((void**)&cK,      g_cK);
    cudaGetSymbolAddress((void**)&diff,    g_diff);
    cudaGetSymbolAddress((void**)&ff,      g_ff);
    cudaGetSymbolAddress((void**)&out1,    g_out1);

    const float gate = 1.0f / (1.0f + expf(-0.01f));
    const int attn_smem = (QB*SCP + QB*256) * (int)sizeof(float);   // ~82 KB
    cudaFuncSetAttribute(attn_flash, cudaFuncAttributeMaxDynamicSharedMemorySize,
                         attn_smem);

    embed_kernel<<<SB_, 256>>>(inp, word_emb, h);

    for (int l = 0; l < L_; l++) {
        // q = h @ Wq^T   (4096 x 768 x 768)
        gemm_bf16s<<<dim3(D_/128, SB_/128), 256>>>(h, Wq + (size_t)l*D_*D_, nullptr, q,
                                                   SB_, D_, D_, 0);
        // kv = h @ Wkv^T (4096 x 1536 x 768)
        gemm_bf16s<<<dim3(2*D_/128, SB_/128), 256>>>(h, Wkv + (size_t)l*2*D_*D_, nullptr, kv,
                                                     SB_, 2*D_, D_, 0);
        // local causal attention (16 queries per block)
        attn_flash<<<dim3(S_/QB, B_*NH_), 256, attn_smem>>>(
            q, kv /*k*/, kv + D_ /*v*/, attn, D_, 2*D_, D_);
        // memory retrieval + delta + fused gated combine (content = gated mix)
        mem_retrieve<<<dim3(B_*NH_, 8), 256>>>(q, kv /*k*/, kv + D_ /*v*/,
                                               memory, mem_norm, l,
                                               attn, gate,
                                               content, diff, cK, D_, 2*D_);
        // memory + norm updates straight into d_out
        mem_update<<<B_*NH_, 256>>>(cK, diff, memory, l, outM);
        norm_update<<<B_*NH_, 512>>>(cK, mem_norm, l, outN);
        // Wo projection (content holds the gated attention mix; write into attn)
        gemm_bf16s<<<dim3(D_/128, SB_/128), 256>>>(content, Wo + (size_t)l*D_*D_, nullptr, attn,
                                                   SB_, D_, D_, 0);
        // ln1: out1 = LN(h + proj)
        ln_kernel<<<SB_, 256>>>(h, attn, ln1g + l*D_, ln1b + l*D_, out1);
        // ff1 = relu(out1 @ W1^T + b1)  (4096 x 3072 x 768)
        gemm_bf16s<<<dim3(DI_/128, SB_/128), 256>>>(out1, ffW1 + (size_t)l*DI_*D_, ffb1 + l*DI_,
                                                    ff, SB_, DI_, D_, 1);
        // ff2 = ff1 @ W2^T + b2         (4096 x 768 x 3072)
        gemm_bf16s<<<dim3(D_/128, SB_/128), 256>>>(ff, ffW2 + (size_t)l*D_*DI_, ffb2 + l*D_,
                                                   content, SB_, D_, DI_, 2);
        // ln2: h = LN(out1 + ff2)
        ln_kernel<<<SB_, 256>>>(out1, content, ln2g + l*D_, ln2b + l*D_, h);
    }

    cudaMemcpyAsync(outH, h, (size_t)SB_*D_*sizeof(float),
                    cudaMemcpyDeviceToDevice);
}

// round 6
// speedup vs baseline: 3.8511x; 1.2333x over previous
#include <cuda_runtime.h>
#include <cuda_bf16.h>
#include <math.h>
#include <stdint.h>

// Problem dims
#define S_  1024
#define B_  4
#define D_  768
#define NH_ 12
#define DH_ 64
#define L_  4
#define DI_ 3072
#define SB_ (S_*B_)

// ---------------- scratch (device globals; no allocation allowed) ------------
__device__ float g_h[SB_*D_];
__device__ float g_q[SB_*D_];
__device__ float g_kv[SB_*2*D_];
__device__ float g_attn[SB_*D_];
__device__ float g_content[SB_*D_];
__device__ float g_cK[SB_*D_];
__device__ float g_diff[SB_*D_];
__device__ float g_ff[SB_*DI_];
__device__ float g_out1[SB_*D_];

// pack two floats into bf16x2 (lo half = first arg)
__device__ __forceinline__ uint32_t pack_bf2(float a, float b) {
    __nv_bfloat162 h = __floats2bfloat162_rn(a, b);
    return *(uint32_t*)&h;
}

__device__ __forceinline__ void mma16816(float* d, const uint32_t* a,
                                         uint32_t b0, uint32_t b1) {
    asm volatile(
        "mma.sync.aligned.m16n8k16.row.col.f32.bf16.bf16.f32 "
        "{%0,%1,%2,%3}, {%4,%5,%6,%7}, {%8,%9}, {%0,%1,%2,%3};"
        : "+f"(d[0]), "+f"(d[1]), "+f"(d[2]), "+f"(d[3])
        : "r"(a[0]), "r"(a[1]), "r"(a[2]), "r"(a[3]), "r"(b0), "r"(b1));
}

// ---------------- embedding + sinusoidal positional encoding -----------------
__global__ void embed_kernel(const int* __restrict__ inp,
                             const float* __restrict__ we,
                             float* __restrict__ h)
{
    int row = blockIdx.x;          // row = s*B + b
    int s = row / B_;
    int b = row % B_;
    int t = threadIdx.x;           // 256
    int tok = inp[s*B_ + b];
    float pos = (float)(S_ - 1 - s);
    const float lg = logf(10000.0f);
    for (int d = t; d < D_; d += 256) {
        int i = (d < 384) ? d : d - 384;
        float freq = expf(-((float)(2*i) / (float)D_) * lg);
        float ang = pos * freq;
        float pe = (d < 384) ? sinf(ang) : cosf(ang);
        h[(size_t)row*D_ + d] = we[(size_t)tok*D_ + d] * 27.712812921102035f + pe;
    }
}

// ---------------- NT GEMM (bf16 tensor cores, hi/lo split = ~fp32) -----------
#define KT 16
#define KP 20
__global__ __launch_bounds__(256) void gemm_bf16s(
    const float* __restrict__ A, const float* __restrict__ Bm,
    const float* __restrict__ bias, float* __restrict__ C,
    int M, int N, int K, int epi)
{
    __shared__ __align__(16) uint32_t As[2][128][KP];
    __shared__ __align__(16) uint32_t Bs[2][128][KP];
    int tid  = threadIdx.x;
    int m0 = blockIdx.y * 128, n0 = blockIdx.x * 128;
    int warp = tid >> 5, lane = tid & 31;
    int wm = warp >> 2, wn = warp & 3;        // 2 x 4 warp grid
    int r0 = lane >> 2, cq = lane & 3;

    int lr = tid >> 2;          // 0..63
    int lc = (tid & 3) * 4;     // 0,4,8,12 (k offset in floats)
    int wc = lc >> 1;           // word col: 0,2,4,6
    const float* Ap = A  + (size_t)(m0 + lr)*K + lc;
    const float* Bp = Bm + (size_t)(n0 + lr)*K + lc;

    float acc[16][4];
    #pragma unroll
    for (int i = 0; i < 16; i++)
        #pragma unroll
        for (int j = 0; j < 4; j++) acc[i][j] = 0.f;

    #define STORE_SPLIT(dst, row, vec)                                          \
    {                                                                           \
        float4 _v = (vec);                                                      \
        float hx = __bfloat162float(__float2bfloat16_rn(_v.x));                 \
        float hy = __bfloat162float(__float2bfloat16_rn(_v.y));                 \
        float hz = __bfloat162float(__float2bfloat16_rn(_v.z));                 \
        float hw = __bfloat162float(__float2bfloat16_rn(_v.w));                 \
        dst[row][wc+0] = pack_bf2(hx, hy);                                      \
        dst[row][wc+1] = pack_bf2(hz, hw);                                      \
        dst[row][8+wc+0] = pack_bf2(_v.x - hx, _v.y - hy);                      \
        dst[row][8+wc+1] = pack_bf2(_v.z - hz, _v.w - hw);                      \
    }

    {
        float4 a0v = *(const float4*)Ap;
        float4 a1v = *(const float4*)(Ap + (size_t)64*K);
        float4 b0v = *(const float4*)Bp;
        float4 b1v = *(const float4*)(Bp + (size_t)64*K);
        STORE_SPLIT(As[0], lr,      a0v);
        STORE_SPLIT(As[0], lr + 64, a1v);
        STORE_SPLIT(Bs[0], lr,      b0v);
        STORE_SPLIT(Bs[0], lr + 64, b1v);
    }
    __syncthreads();

    int buf = 0;
    for (int k0 = KT; k0 < K + KT; k0 += KT) {
        bool more = (k0 < K);
        float4 a0v, a1v, b0v, b1v;
        if (more) {
            a0v = *(const float4*)(Ap + k0);
            a1v = *(const float4*)(Ap + (size_t)64*K + k0);
            b0v = *(const float4*)(Bp + k0);
            b1v = *(const float4*)(Bp + (size_t)64*K + k0);
        }
        uint32_t ah[4][4], al[4][4], bh[4][2], bl[4][2];
        #pragma unroll
        for (int mi = 0; mi < 4; mi++) {
            int mr = wm*64 + mi*16 + r0;
            ah[mi][0] = As[buf][mr    ][cq];
            ah[mi][1] = As[buf][mr + 8][cq];
            ah[mi][2] = As[buf][mr    ][cq + 4];
            ah[mi][3] = As[buf][mr + 8][cq + 4];
            al[mi][0] = As[buf][mr    ][8 + cq];
            al[mi][1] = As[buf][mr + 8][8 + cq];
            al[mi][2] = As[buf][mr    ][8 + cq + 4];
            al[mi][3] = As[buf][mr + 8][8 + cq + 4];
        }
        #pragma unroll
        for (int ni = 0; ni < 4; ni++) {
            int nr = wn*32 + ni*8 + r0;
            bh[ni][0] = Bs[buf][nr][cq];
            bh[ni][1] = Bs[buf][nr][cq + 4];
            bl[ni][0] = Bs[buf][nr][8 + cq];
            bl[ni][1] = Bs[buf][nr][8 + cq + 4];
        }
        #pragma unroll
        for (int mi = 0; mi < 4; mi++)
            #pragma unroll
            for (int ni = 0; ni < 4; ni++) {
                float* d = acc[mi*4 + ni];
                mma16816(d, ah[mi], bh[ni][0], bh[ni][1]);   // hi * hi
                mma16816(d, ah[mi], bl[ni][0], bl[ni][1]);   // hi * lo
                mma16816(d, al[mi], bh[ni][0], bh[ni][1]);   // lo * hi
            }
        if (more) {
            int nb = buf ^ 1;
            STORE_SPLIT(As[nb], lr,      a0v);
            STORE_SPLIT(As[nb], lr + 64, a1v);
            STORE_SPLIT(Bs[nb], lr,      b0v);
            STORE_SPLIT(Bs[nb], lr + 64, b1v);
            __syncthreads();
            buf = nb;
        }
    }
    #undef STORE_SPLIT

    #pragma unroll
    for (int mi = 0; mi < 4; mi++) {
        int m = m0 + wm*64 + mi*16 + r0;
        #pragma unroll
        for (int ni = 0; ni < 4; ni++) {
            int n = n0 + wn*32 + ni*8 + 2*cq;
            float* d = acc[mi*4 + ni];
            float2 v0 = {d[0], d[1]};
            float2 v1 = {d[2], d[3]};
            if (epi == 1) {
                float b0v = bias[n], b1v = bias[n+1];
                v0.x = fmaxf(v0.x + b0v, 0.f); v0.y = fmaxf(v0.y + b1v, 0.f);
                v1.x = fmaxf(v1.x + b0v, 0.f); v1.y = fmaxf(v1.y + b1v, 0.f);
            } else if (epi == 2) {
                float b0v = bias[n], b1v = bias[n+1];
                v0.x += b0v; v0.y += b1v;
                v1.x += b0v; v1.y += b1v;
            }
            *(float2*)(C + (size_t)m*N + n)       = v0;
            *(float2*)(C + (size_t)(m+8)*N + n)   = v1;
        }
    }
}

// ------------- tensor-core flash attention (bf16 hi/lo, fp32 acc) -------------
// Block: 128 queries of one head (8 warps x 16 rows). Iterates 64-key tiles.
// K in smem [key][dim-words] (hi 0..31, lo 32..63, pitch 68).
// V^T in smem [dim][keypair-words] (hi 0..31, lo 32..63, pitch 68).
// Score C-frags repack in-register into P A-frags (flash-2 layout identity).
__global__ __launch_bounds__(256) void attn_mma(
    const float* __restrict__ q, const float* __restrict__ k,
    const float* __restrict__ v, float* __restrict__ o,
    int qS, int kvS, int oS)
{
    int qt = 7 - (int)blockIdx.x;          // big-work blocks first
    int bn = blockIdx.y;
    int b = bn / NH_, n = bn % NH_;
    int col0 = n * DH_;
    int t = threadIdx.x, lane = t & 31, warp = t >> 5;
    int r0 = lane >> 2, cq = lane & 3;

    __shared__ __align__(16) uint32_t Ks[64][68];
    __shared__ __align__(16) uint32_t Vt[64][68];

    int qrow = qt*128 + warp*16;

    // Q fragments (hi/lo) straight from global; held all kernel
    uint32_t qh[4][4], ql[4][4];
    #pragma unroll
    for (int ks = 0; ks < 4; ks++) {
        int cb = ks*16 + 2*cq;
        #pragma unroll
        for (int u = 0; u < 4; u++) {
            int rr = qrow + r0 + ((u & 1) ? 8 : 0);
            int cc = cb + ((u & 2) ? 8 : 0);
            float2 qv = *(const float2*)(q + ((size_t)rr*B_ + b)*qS + col0 + cc);
            float hx = __bfloat162float(__float2bfloat16_rn(qv.x));
            float hy = __bfloat162float(__float2bfloat16_rn(qv.y));
            qh[ks][u] = pack_bf2(hx, hy);
            ql[ks][u] = pack_bf2(qv.x - hx, qv.y - hy);
        }
    }

    float Oc[8][4];
    #pragma unroll
    for (int i = 0; i < 8; i++)
        #pragma unroll
        for (int j = 0; j < 4; j++) Oc[i][j] = 0.f;
    float m0 = -3.4e38f, m8 = -3.4e38f, l0 = 0.f, l8 = 0.f;

    int nkt = 2*qt + 2;
    for (int kt = 0; kt < nkt; kt++) {
        // ---- load K tile [64 keys][64 dims] ----
        for (int idx = t; idx < 64*16; idx += 256) {
            int key = idx >> 4, c = idx & 15;
            float4 kv4 = *(const float4*)(k + ((size_t)(kt*64+key)*B_ + b)*kvS
                                            + col0 + 4*c);
            float hx = __bfloat162float(__float2bfloat16_rn(kv4.x));
            float hy = __bfloat162float(__float2bfloat16_rn(kv4.y));
            float hz = __bfloat162float(__float2bfloat16_rn(kv4.z));
            float hw = __bfloat162float(__float2bfloat16_rn(kv4.w));
            Ks[key][2*c  ] = pack_bf2(hx, hy);
            Ks[key][2*c+1] = pack_bf2(hz, hw);
            Ks[key][32 + 2*c  ] = pack_bf2(kv4.x - hx, kv4.y - hy);
            Ks[key][32 + 2*c+1] = pack_bf2(kv4.z - hz, kv4.w - hw);
        }
        // ---- load V^T tile: Vt[dim][keypair] ----
        #pragma unroll
        for (int it = 0; it < 4; it++) {
            int idx = t + 256*it;           // 0..1023
            int j = idx >> 5;               // keypair 0..31
            int d = idx & 31;               // dimpair 0..31
            const float* vp0 = v + ((size_t)(kt*64 + 2*j)*B_ + b)*kvS + col0 + 2*d;
            float2 va = *(const float2*)vp0;
            float2 vb = *(const float2*)(vp0 + (size_t)B_*kvS);
            float hax = __bfloat162float(__float2bfloat16_rn(va.x));
            float hay = __bfloat162float(__float2bfloat16_rn(va.y));
            float hbx = __bfloat162float(__float2bfloat16_rn(vb.x));
            float hby = __bfloat162float(__float2bfloat16_rn(vb.y));
            Vt[2*d  ][j] = pack_bf2(hax, hbx);
            Vt[2*d+1][j] = pack_bf2(hay, hby);
            Vt[2*d  ][32 + j] = pack_bf2(va.x - hax, vb.x - hbx);
            Vt[2*d+1][32 + j] = pack_bf2(va.y - hay, vb.y - hby);
        }
        __syncthreads();

        // ---- scores: S = Q K^T (3-mma hi/lo split) ----
        float sc[8][4];
        #pragma unroll
        for (int i = 0; i < 8; i++)
            #pragma unroll
            for (int j = 0; j < 4; j++) sc[i][j] = 0.f;
        #pragma unroll
        for (int ks = 0; ks < 4; ks++) {
            #pragma unroll
            for (int ni = 0; ni < 8; ni++) {
                int nr = ni*8 + r0;
                uint32_t bh0 = Ks[nr][cq + 8*ks];
                uint32_t bh1 = Ks[nr][cq + 8*ks + 4];
                uint32_t bl0 = Ks[nr][32 + cq + 8*ks];
                uint32_t bl1 = Ks[nr][32 + cq + 8*ks + 4];
                mma16816(sc[ni], qh[ks], bh0, bh1);
                mma16816(sc[ni], qh[ks], bl0, bl1);
                mma16816(sc[ni], ql[ks], bh0, bh1);
            }
        }

        // ---- scale + causal mask + online softmax ----
        const float scale = 0.125f;
        bool diag = (kt >= 2*qt);
        int rg0 = qrow + r0, rg8 = rg0 + 8;
        float tm0 = -3.4e38f, tm8 = -3.4e38f;
        #pragma unroll
        for (int ni = 0; ni < 8; ni++) {
            float s0 = sc[ni][0]*scale, s1 = sc[ni][1]*scale;
            float s2 = sc[ni][2]*scale, s3 = sc[ni][3]*scale;
            if (diag) {
                int colg = kt*64 + ni*8 + 2*cq;
                if (colg     > rg0) s0 = -3.4e38f;
                if (colg + 1 > rg0) s1 = -3.4e38f;
                if (colg     > rg8) s2 = -3.4e38f;
                if (colg + 1 > rg8) s3 = -3.4e38f;
            }
            sc[ni][0] = s0; sc[ni][1] = s1; sc[ni][2] = s2; sc[ni][3] = s3;
            tm0 = fmaxf(tm0, fmaxf(s0, s1));
            tm8 = fmaxf(tm8, fmaxf(s2, s3));
        }
        tm0 = fmaxf(tm0, __shfl_xor_sync(0xffffffff, tm0, 1));
        tm0 = fmaxf(tm0, __shfl_xor_sync(0xffffffff, tm0, 2));
        tm8 = fmaxf(tm8, __shfl_xor_sync(0xffffffff, tm8, 1));
        tm8 = fmaxf(tm8, __shfl_xor_sync(0xffffffff, tm8, 2));
        float mn0 = fmaxf(m0, tm0), mn8 = fmaxf(m8, tm8);
        float al0 = __expf(m0 - mn0), al8 = __expf(m8 - mn8);
        m0 = mn0; m8 = mn8;
        float rs0 = 0.f, rs8 = 0.f;
        #pragma unroll
        for (int ni = 0; ni < 8; ni++) {
            float p0 = __expf(sc[ni][0] - mn0);
            float p1 = __expf(sc[ni][1] - mn0);
            float p2 = __expf(sc[ni][2] - mn8);
            float p3 = __expf(sc[ni][3] - mn8);
            sc[ni][0] = p0; sc[ni][1] = p1; sc[ni][2] = p2; sc[ni][3] = p3;
            rs0 += p0 + p1; rs8 += p2 + p3;
        }
        rs0 += __shfl_xor_sync(0xffffffff, rs0, 1);
        rs0 += __shfl_xor_sync(0xffffffff, rs0, 2);
        rs8 += __shfl_xor_sync(0xffffffff, rs8, 1);
        rs8 += __shfl_xor_sync(0xffffffff, rs8, 2);
        l0 = l0*al0 + rs0;
        l8 = l8*al8 + rs8;
        #pragma unroll
        for (int ni = 0; ni < 8; ni++) {
            Oc[ni][0] *= al0; Oc[ni][1] *= al0;
            Oc[ni][2] *= al8; Oc[ni][3] *= al8;
        }

        // ---- repack P (score C-frags -> A-frags), hi/lo ----
        uint32_t ph[4][4], pl[4][4];
        #pragma unroll
        for (int ks2 = 0; ks2 < 4; ks2++) {
            float x0 = sc[2*ks2][0],   x1 = sc[2*ks2][1];
            float x2 = sc[2*ks2][2],   x3 = sc[2*ks2][3];
            float y0 = sc[2*ks2+1][0], y1 = sc[2*ks2+1][1];
            float y2 = sc[2*ks2+1][2], y3 = sc[2*ks2+1][3];
            float hx0 = __bfloat162float(__float2bfloat16_rn(x0));
            float hx1 = __bfloat162float(__float2bfloat16_rn(x1));
            float hx2 = __bfloat162float(__float2bfloat16_rn(x2));
            float hx3 = __bfloat162float(__float2bfloat16_rn(x3));
            float hy0 = __bfloat162float(__float2bfloat16_rn(y0));
            float hy1 = __bfloat162float(__float2bfloat16_rn(y1));
            float hy2 = __bfloat162float(__float2bfloat16_rn(y2));
            float hy3 = __bfloat162float(__float2bfloat16_rn(y3));
            ph[ks2][0] = pack_bf2(hx0, hx1);
            ph[ks2][1] = pack_bf2(hx2, hx3);
            ph[ks2][2] = pack_bf2(hy0, hy1);
            ph[ks2][3] = pack_bf2(hy2, hy3);
            pl[ks2][0] = pack_bf2(x0 - hx0, x1 - hx1);
            pl[ks2][1] = pack_bf2(x2 - hx2, x3 - hx3);
            pl[ks2][2] = pack_bf2(y0 - hy0, y1 - hy1);
            pl[ks2][3] = pack_bf2(y2 - hy2, y3 - hy3);
        }

        // ---- O += P V (3-mma hi/lo split) ----
        #pragma unroll
        for (int ks2 = 0; ks2 < 4; ks2++) {
            #pragma unroll
            for (int ni = 0; ni < 8; ni++) {
                int nr = ni*8 + r0;
                uint32_t vh0 = Vt[nr][cq + 8*ks2];
                uint32_t vh1 = Vt[nr][cq + 8*ks2 + 4];
                uint32_t vl0 = Vt[nr][32 + cq + 8*ks2];
                uint32_t vl1 = Vt[nr][32 + cq + 8*ks2 + 4];
                mma16816(Oc[ni], ph[ks2], vh0, vh1);
                mma16816(Oc[ni], ph[ks2], vl0, vl1);
                mma16816(Oc[ni], pl[ks2], vh0, vh1);
            }
        }
        __syncthreads();
    }

    // ---- epilogue: normalize + store ----
    float i0 = 1.f / l0, i8 = 1.f / l8;
    #pragma unroll
    for (int ni = 0; ni < 8; ni++) {
        int cc = col0 + ni*8 + 2*cq;
        float2 w0 = {Oc[ni][0]*i0, Oc[ni][1]*i0};
        float2 w8 = {Oc[ni][2]*i8, Oc[ni][3]*i8};
        *(float2*)(o + ((size_t)(qrow + r0    )*B_ + b)*oS + cc) = w0;
        *(float2*)(o + ((size_t)(qrow + r0 + 8)*B_ + b)*oS + cc) = w8;
    }
}

// -------- memory retrieval + delta + fused gated combine ----------------------
__global__ __launch_bounds__(256) void mem_retrieve(
    const float* __restrict__ q, const float* __restrict__ kp,
    const float* __restrict__ vp, const float* __restrict__ memory,
    const float* __restrict__ mem_norm, int l,
    const float* __restrict__ attn, float gate,
    float* __restrict__ content, float* __restrict__ diff, float* __restrict__ cKout,
    int qS, int kvS)
{
    int bn = blockIdx.x;
    int b = bn / NH_, n = bn % NH_;
    int chunk = blockIdx.y;          // 8 chunks of 128 s-values
    int t = threadIdx.x;

    __shared__ float Msh[DH_][DH_+1];
    __shared__ float normsh[DH_];
    __shared__ float cqsh[4][DH_];
    __shared__ float cksh[4][DH_];

    const float* Mg = memory + ((size_t)(l*B_ + b)*NH_ + n)*DH_*DH_;
    for (int idx = t; idx < DH_*DH_; idx += 256) Msh[idx >> 6][idx & 63] = Mg[idx];
    if (t < DH_) normsh[t] = mem_norm[((size_t)(l*B_ + b)*NH_ + n)*DH_ + t];
    __syncthreads();

    int g = t >> 6, d = t & 63;
    int col = n * DH_;
    for (int it = 0; it < 32; ++it) {
        int s = chunk*128 + it*4 + g;
        size_t row = (size_t)(s*B_ + b);
        float qvl = q [row*qS  + col + d];
        float vvl = vp[row*kvS + col + d];
        float cq = qvl > 0.f ? qvl + 1.f : __expf(qvl);
        float ck = vvl > 0.f ? vvl + 1.f : __expf(vvl);
        cqsh[g][d] = cq; cksh[g][d] = ck;
        __syncthreads();
        float accA = 0.f, accB = 0.f, denQ = 0.f, denK = 0.f;
        #pragma unroll 8
        for (int kk = 0; kk < DH_; kk++) {
            float mq = Msh[kk][d];
            accA += cqsh[g][kk] * mq;
            accB += cksh[g][kk] * mq;
            denQ += cqsh[g][kk] * normsh[kk];
            denK += cksh[g][kk] * normsh[kk];
        }
        size_t oidx = row*D_ + col + d;
        content[oidx] = gate * (accA / denQ) + (1.f - gate) * attn[oidx];
        diff[oidx]    = kp[row*kvS + col + d] - accB / denK;
        cKout[oidx]   = ck;
        __syncthreads();
    }
}

// -------- memory update: newM[k][v] = M[k][v] + sum_s cK[s,k]*diff[s,v] ------
__global__ __launch_bounds__(256) void mem_update(
    const float* __restrict__ cK, const float* __restrict__ diff,
    const float* __restrict__ memory, int l, float* __restrict__ outM)
{
    int bn = blockIdx.x;
    int b = bn / NH_, n = bn % NH_;
    __shared__ float aS[16][DH_];
    __shared__ float bS[16][DH_];
    int t = threadIdx.x;
    int tx = t & 15, ty = t >> 4;
    float acc[4][4] = {};
    int col = n * DH_;
    int r  = t >> 4;
    int c4 = (t & 15) * 4;
    for (int s0 = 0; s0 < S_; s0 += 16) {
        size_t row = (size_t)((s0 + r)*B_ + b);
        *(float4*)&aS[r][c4] = *(const float4*)(cK   + row*D_ + col + c4);
        *(float4*)&bS[r][c4] = *(const float4*)(diff + row*D_ + col + c4);
        __syncthreads();
        #pragma unroll
        for (int ss = 0; ss < 16; ss++) {
            float a[4], bb[4];
            #pragma unroll
            for (int u = 0; u < 4; u++) { a[u] = aS[ss][ty*4+u]; bb[u] = bS[ss][tx*4+u]; }
            #pragma unroll
            for (int i = 0; i < 4; i++)
                #pragma unroll
                for (int j = 0; j < 4; j++)
                    acc[i][j] = fmaf(a[i], bb[j], acc[i][j]);
        }
        __syncthreads();
    }
    const float* Mg = memory + ((size_t)(l*B_ + b)*NH_ + n)*DH_*DH_;
    float*       Og = outM   + ((size_t)(l*B_ + b)*NH_ + n)*DH_*DH_;
    #pragma unroll
    for (int i = 0; i < 4; i++)
        #pragma unroll
        for (int j = 0; j < 4; j++) {
            int kk = ty*4 + i, vv = tx*4 + j;
            Og[kk*DH_ + vv] = Mg[kk*DH_ + vv] + acc[i][j];
        }
}

// -------- norm update: outN = mem_norm + sum_s cK (parallel over s) ----------
__global__ __launch_bounds__(512) void norm_update(
    const float* __restrict__ cK, const float* __restrict__ mem_norm, int l,
    float* __restrict__ outN)
{
    int bn = blockIdx.x;
    int b = bn / NH_, n = bn % NH_;
    int t = threadIdx.x;
    int d = t & 63, sg = t >> 6;   // 8 s-groups
    int col = n * DH_;
    float acc = 0.f;
    for (int s = sg; s < S_; s += 8)
        acc += cK[(size_t)(s*B_ + b)*D_ + col + d];
    __shared__ float red[512];
    red[t] = acc; __syncthreads();
    if (t < 256) red[t] += red[t + 256]; __syncthreads();
    if (t < 128) red[t] += red[t + 128]; __syncthreads();
    if (t < 64) {
        size_t o = ((size_t)(l*B_ + b)*NH_ + n)*DH_ + t;
        outN[o] = mem_norm[o] + red[t] + red[t + 64];
    }
}

// -------- layernorm with residual: out = LN(res + y) --------------------------
__global__ __launch_bounds__(256) void ln_kernel(
    const float* __restrict__ res, const float* __restrict__ y,
    const float* __restrict__ g, const float* __restrict__ bb,
    float* __restrict__ out)
{
    int row = blockIdx.x;
    int t = threadIdx.x;
    __shared__ float red[256];
    size_t base = (size_t)row * D_;
    float x0 = res[base + t      ] + y[base + t      ];
    float x1 = res[base + t + 256] + y[base + t + 256];
    float x2 = res[base + t + 512] + y[base + t + 512];
    red[t] = x0 + x1 + x2; __syncthreads();
    for (int o = 128; o > 0; o >>= 1) { if (t < o) red[t] += red[t+o]; __syncthreads(); }
    float mu = red[0] * (1.f / 768.f); __syncthreads();
    float d0 = x0 - mu, d1 = x1 - mu, d2 = x2 - mu;
    red[t] = d0*d0 + d1*d1 + d2*d2; __syncthreads();
    for (int o = 128; o > 0; o >>= 1) { if (t < o) red[t] += red[t+o]; __syncthreads(); }
    float inv = rsqrtf(red[0] * (1.f / 768.f) + 1e-5f);
    out[base + t      ] = d0 * inv * g[t      ] + bb[t      ];
    out[base + t + 256] = d1 * inv * g[t + 256] + bb[t + 256];
    out[base + t + 512] = d2 * inv * g[t + 512] + bb[t + 512];
}

// ------------------------------- launcher -------------------------------------
extern "C" void kernel_launch(void* const* d_in, const int* in_sizes, int n_in,
                              void* d_out, int out_size)
{
    const int*   inp      = (const int*)  d_in[0];
    const float* word_emb = (const float*)d_in[1];
    const float* Wq       = (const float*)d_in[2];
    const float* Wkv      = (const float*)d_in[3];
    const float* Wo       = (const float*)d_in[4];
    const float* ln1g     = (const float*)d_in[5];
    const float* ln1b     = (const float*)d_in[6];
    const float* ffW1     = (const float*)d_in[7];
    const float* ffb1     = (const float*)d_in[8];
    const float* ffW2     = (const float*)d_in[9];
    const float* ffb2     = (const float*)d_in[10];
    const float* ln2g     = (const float*)d_in[11];
    const float* ln2b     = (const float*)d_in[12];
    const float* memory   = (const float*)d_in[13];
    const float* mem_norm = (const float*)d_in[14];

    float* out  = (float*)d_out;
    float* outH = out;                         // (S,B,D)
    float* outM = out + (size_t)SB_*D_;        // (L,B,NH,DH,DH)
    float* outN = outM + (size_t)L_*B_*NH_*DH_*DH_;  // (L,B,NH,DH)

    float *h, *q, *kv, *attn, *content, *cK, *diff, *ff, *out1;
    cudaGetSymbolAddress((void**)&h,       g_h);
    cudaGetSymbolAddress((void**)&q,       g_q);
    cudaGetSymbolAddress((void**)&kv,      g_kv);
    cudaGetSymbolAddress((void**)&attn,    g_attn);
    cudaGetSymbolAddress((void**)&content, g_content);
    cudaGetSymbolAddress((void**)&cK,      g_cK);
    cudaGetSymbolAddress((void**)&diff,    g_diff);
    cudaGetSymbolAddress((void**)&ff,      g_ff);
    cudaGetSymbolAddress((void**)&out1,    g_out1);

    const float gate = 1.0f / (1.0f + expf(-0.01f));

    embed_kernel<<<SB_, 256>>>(inp, word_emb, h);

    for (int l = 0; l < L_; l++) {
        // q = h @ Wq^T   (4096 x 768 x 768)
        gemm_bf16s<<<dim3(D_/128, SB_/128), 256>>>(h, Wq + (size_t)l*D_*D_, nullptr, q,
                                                   SB_, D_, D_, 0);
        // kv = h @ Wkv^T (4096 x 1536 x 768)
        gemm_bf16s<<<dim3(2*D_/128, SB_/128), 256>>>(h, Wkv + (size_t)l*2*D_*D_, nullptr, kv,
                                                     SB_, 2*D_, D_, 0);
        // local causal attention (tensor-core flash, 128 queries per block)
        attn_mma<<<dim3(8, B_*NH_), 256>>>(q, kv /*k*/, kv + D_ /*v*/, attn,
                                           D_, 2*D_, D_);
        // memory retrieval + delta + fused gated combine (content = gated mix)
        mem_retrieve<<<dim3(B_*NH_, 8), 256>>>(q, kv /*k*/, kv + D_ /*v*/,
                                               memory, mem_norm, l,
                                               attn, gate,
                                               content, diff, cK, D_, 2*D_);
        // memory + norm updates straight into d_out
        mem_update<<<B_*NH_, 256>>>(cK, diff, memory, l, outM);
        norm_update<<<B_*NH_, 512>>>(cK, mem_norm, l, outN);
        // Wo projection (content holds the gated attention mix; write into attn)
        gemm_bf16s<<<dim3(D_/128, SB_/128), 256>>>(content, Wo + (size_t)l*D_*D_, nullptr, attn,
                                                   SB_, D_, D_, 0);
        // ln1: out1 = LN(h + proj)
        ln_kernel<<<SB_, 256>>>(h, attn, ln1g + l*D_, ln1b + l*D_, out1);
        // ff1 = relu(out1 @ W1^T + b1)  (4096 x 3072 x 768)
        gemm_bf16s<<<dim3(DI_/128, SB_/128), 256>>>(out1, ffW1 + (size_t)l*DI_*D_, ffb1 + l*DI_,
                                                    ff, SB_, DI_, D_, 1);
        // ff2 = ff1 @ W2^T + b2         (4096 x 768 x 3072)
        gemm_bf16s<<<dim3(D_/128, SB_/128), 256>>>(ff, ffW2 + (size_t)l*D_*DI_, ffb2 + l*D_,
                                                   content, SB_, D_, DI_, 2);
        // ln2: h = LN(out1 + ff2)
        ln_kernel<<<SB_, 256>>>(out1, content, ln2g + l*D_, ln2b + l*D_, h);
    }

    cudaMemcpyAsync(outH, h, (size_t)SB_*D_*sizeof(float),
                    cudaMemcpyDeviceToDevice);
}

// round 8
// speedup vs baseline: 3.8725x; 1.0056x over previous
#include <cuda_runtime.h>
#include <cuda_bf16.h>
#include <math.h>
#include <stdint.h>

// Problem dims
#define S_  1024
#define B_  4
#define D_  768
#define NH_ 12
#define DH_ 64
#define L_  4
#define DI_ 3072
#define SB_ (S_*B_)

// ---------------- scratch (device globals; no allocation allowed) ------------
__device__ float g_h[SB_*D_];
__device__ float g_q[SB_*D_];
__device__ float g_kv[SB_*2*D_];
__device__ float g_attn[SB_*D_];
__device__ float g_content[SB_*D_];
__device__ float g_cK[SB_*D_];
__device__ float g_diff[SB_*D_];
__device__ float g_ff[SB_*DI_];
__device__ float g_out1[SB_*D_];

// pack two floats into bf16x2 (lo half = first arg)
__device__ __forceinline__ uint32_t pack_bf2(float a, float b) {
    __nv_bfloat162 h = __floats2bfloat162_rn(a, b);
    return *(uint32_t*)&h;
}

__device__ __forceinline__ void mma16816(float* d, const uint32_t* a,
                                         uint32_t b0, uint32_t b1) {
    asm volatile(
        "mma.sync.aligned.m16n8k16.row.col.f32.bf16.bf16.f32 "
        "{%0,%1,%2,%3}, {%4,%5,%6,%7}, {%8,%9}, {%0,%1,%2,%3};"
        : "+f"(d[0]), "+f"(d[1]), "+f"(d[2]), "+f"(d[3])
        : "r"(a[0]), "r"(a[1]), "r"(a[2]), "r"(a[3]), "r"(b0), "r"(b1));
}

// ---------------- embedding + sinusoidal positional encoding -----------------
__global__ void embed_kernel(const int* __restrict__ inp,
                             const float* __restrict__ we,
                             float* __restrict__ h)
{
    int row = blockIdx.x;          // row = s*B + b
    int s = row / B_;
    int b = row % B_;
    int t = threadIdx.x;           // 256
    int tok = inp[s*B_ + b];
    float pos = (float)(S_ - 1 - s);
    const float lg = logf(10000.0f);
    for (int d = t; d < D_; d += 256) {
        int i = (d < 384) ? d : d - 384;
        float freq = expf(-((float)(2*i) / (float)D_) * lg);
        float ang = pos * freq;
        float pe = (d < 384) ? sinf(ang) : cosf(ang);
        h[(size_t)row*D_ + d] = we[(size_t)tok*D_ + d] * 27.712812921102035f + pe;
    }
}

// ---------------- NT GEMM (bf16 tensor cores, hi/lo split = ~fp32) -----------
// Term-major mma ordering: between two writes to the same accumulator there
// are 15 independent HMMAs, hiding the ~24-32cy result latency.
#define KT 16
#define KP 20
__global__ __launch_bounds__(256) void gemm_bf16s(
    const float* __restrict__ A, const float* __restrict__ Bm,
    const float* __restrict__ bias, float* __restrict__ C,
    int M, int N, int K, int epi)
{
    __shared__ __align__(16) uint32_t As[2][128][KP];
    __shared__ __align__(16) uint32_t Bs[2][128][KP];
    int tid  = threadIdx.x;
    int m0 = blockIdx.y * 128, n0 = blockIdx.x * 128;
    int warp = tid >> 5, lane = tid & 31;
    int wm = warp >> 2, wn = warp & 3;        // 2 x 4 warp grid
    int r0 = lane >> 2, cq = lane & 3;

    int lr = tid >> 2;          // 0..63
    int lc = (tid & 3) * 4;     // 0,4,8,12 (k offset in floats)
    int wc = lc >> 1;           // word col: 0,2,4,6
    const float* Ap = A  + (size_t)(m0 + lr)*K + lc;
    const float* Bp = Bm + (size_t)(n0 + lr)*K + lc;

    float acc[16][4];
    #pragma unroll
    for (int i = 0; i < 16; i++)
        #pragma unroll
        for (int j = 0; j < 4; j++) acc[i][j] = 0.f;

    #define STORE_SPLIT(dst, row, vec)                                          \
    {                                                                           \
        float4 _v = (vec);                                                      \
        float hx = __bfloat162float(__float2bfloat16_rn(_v.x));                 \
        float hy = __bfloat162float(__float2bfloat16_rn(_v.y));                 \
        float hz = __bfloat162float(__float2bfloat16_rn(_v.z));                 \
        float hw = __bfloat162float(__float2bfloat16_rn(_v.w));                 \
        dst[row][wc+0] = pack_bf2(hx, hy);                                      \
        dst[row][wc+1] = pack_bf2(hz, hw);                                      \
        dst[row][8+wc+0] = pack_bf2(_v.x - hx, _v.y - hy);                      \
        dst[row][8+wc+1] = pack_bf2(_v.z - hz, _v.w - hw);                      \
    }

    {
        float4 a0v = *(const float4*)Ap;
        float4 a1v = *(const float4*)(Ap + (size_t)64*K);
        float4 b0v = *(const float4*)Bp;
        float4 b1v = *(const float4*)(Bp + (size_t)64*K);
        STORE_SPLIT(As[0], lr,      a0v);
        STORE_SPLIT(As[0], lr + 64, a1v);
        STORE_SPLIT(Bs[0], lr,      b0v);
        STORE_SPLIT(Bs[0], lr + 64, b1v);
    }
    __syncthreads();

    int buf = 0;
    for (int k0 = KT; k0 < K + KT; k0 += KT) {
        bool more = (k0 < K);
        float4 a0v, a1v, b0v, b1v;
        if (more) {
            a0v = *(const float4*)(Ap + k0);
            a1v = *(const float4*)(Ap + (size_t)64*K + k0);
            b0v = *(const float4*)(Bp + k0);
            b1v = *(const float4*)(Bp + (size_t)64*K + k0);
        }
        uint32_t ah[4][4], al[4][4], bh[4][2], bl[4][2];
        #pragma unroll
        for (int mi = 0; mi < 4; mi++) {
            int mr = wm*64 + mi*16 + r0;
            ah[mi][0] = As[buf][mr    ][cq];
            ah[mi][1] = As[buf][mr + 8][cq];
            ah[mi][2] = As[buf][mr    ][cq + 4];
            ah[mi][3] = As[buf][mr + 8][cq + 4];
            al[mi][0] = As[buf][mr    ][8 + cq];
            al[mi][1] = As[buf][mr + 8][8 + cq];
            al[mi][2] = As[buf][mr    ][8 + cq + 4];
            al[mi][3] = As[buf][mr + 8][8 + cq + 4];
        }
        #pragma unroll
        for (int ni = 0; ni < 4; ni++) {
            int nr = wn*32 + ni*8 + r0;
            bh[ni][0] = Bs[buf][nr][cq];
            bh[ni][1] = Bs[buf][nr][cq + 4];
            bl[ni][0] = Bs[buf][nr][8 + cq];
            bl[ni][1] = Bs[buf][nr][8 + cq + 4];
        }
        // term-major: all hi*hi, then all hi*lo, then all lo*hi
        #pragma unroll
        for (int mi = 0; mi < 4; mi++)
            #pragma unroll
            for (int ni = 0; ni < 4; ni++)
                mma16816(acc[mi*4 + ni], ah[mi], bh[ni][0], bh[ni][1]);
        #pragma unroll
        for (int mi = 0; mi < 4; mi++)
            #pragma unroll
            for (int ni = 0; ni < 4; ni++)
                mma16816(acc[mi*4 + ni], ah[mi], bl[ni][0], bl[ni][1]);
        #pragma unroll
        for (int mi = 0; mi < 4; mi++)
            #pragma unroll
            for (int ni = 0; ni < 4; ni++)
                mma16816(acc[mi*4 + ni], al[mi], bh[ni][0], bh[ni][1]);
        if (more) {
            int nb = buf ^ 1;
            STORE_SPLIT(As[nb], lr,      a0v);
            STORE_SPLIT(As[nb], lr + 64, a1v);
            STORE_SPLIT(Bs[nb], lr,      b0v);
            STORE_SPLIT(Bs[nb], lr + 64, b1v);
            __syncthreads();
            buf = nb;
        }
    }
    #undef STORE_SPLIT

    #pragma unroll
    for (int mi = 0; mi < 4; mi++) {
        int m = m0 + wm*64 + mi*16 + r0;
        #pragma unroll
        for (int ni = 0; ni < 4; ni++) {
            int n = n0 + wn*32 + ni*8 + 2*cq;
            float* d = acc[mi*4 + ni];
            float2 v0 = {d[0], d[1]};
            float2 v1 = {d[2], d[3]};
            if (epi == 1) {
                float b0v = bias[n], b1v = bias[n+1];
                v0.x = fmaxf(v0.x + b0v, 0.f); v0.y = fmaxf(v0.y + b1v, 0.f);
                v1.x = fmaxf(v1.x + b0v, 0.f); v1.y = fmaxf(v1.y + b1v, 0.f);
            } else if (epi == 2) {
                float b0v = bias[n], b1v = bias[n+1];
                v0.x += b0v; v0.y += b1v;
                v1.x += b0v; v1.y += b1v;
            }
            *(float2*)(C + (size_t)m*N + n)       = v0;
            *(float2*)(C + (size_t)(m+8)*N + n)   = v1;
        }
    }
}

// ------------- tensor-core flash attention (bf16 hi/lo, fp32 acc) -------------
__global__ __launch_bounds__(256) void attn_mma(
    const float* __restrict__ q, const float* __restrict__ k,
    const float* __restrict__ v, float* __restrict__ o,
    int qS, int kvS, int oS)
{
    int qt = 7 - (int)blockIdx.x;          // big-work blocks first
    int bn = blockIdx.y;
    int b = bn / NH_, n = bn % NH_;
    int col0 = n * DH_;
    int t = threadIdx.x, lane = t & 31, warp = t >> 5;
    int r0 = lane >> 2, cq = lane & 3;

    __shared__ __align__(16) uint32_t Ks[64][68];
    __shared__ __align__(16) uint32_t Vt[64][68];

    int qrow = qt*128 + warp*16;

    uint32_t qh[4][4], ql[4][4];
    #pragma unroll
    for (int ks = 0; ks < 4; ks++) {
        int cb = ks*16 + 2*cq;
        #pragma unroll
        for (int u = 0; u < 4; u++) {
            int rr = qrow + r0 + ((u & 1) ? 8 : 0);
            int cc = cb + ((u & 2) ? 8 : 0);
            float2 qv = *(const float2*)(q + ((size_t)rr*B_ + b)*qS + col0 + cc);
            float hx = __bfloat162float(__float2bfloat16_rn(qv.x));
            float hy = __bfloat162float(__float2bfloat16_rn(qv.y));
            qh[ks][u] = pack_bf2(hx, hy);
            ql[ks][u] = pack_bf2(qv.x - hx, qv.y - hy);
        }
    }

    float Oc[8][4];
    #pragma unroll
    for (int i = 0; i < 8; i++)
        #pragma unroll
        for (int j = 0; j < 4; j++) Oc[i][j] = 0.f;
    float m0 = -3.4e38f, m8 = -3.4e38f, l0 = 0.f, l8 = 0.f;

    int nkt = 2*qt + 2;
    for (int kt = 0; kt < nkt; kt++) {
        for (int idx = t; idx < 64*16; idx += 256) {
            int key = idx >> 4, c = idx & 15;
            float4 kv4 = *(const float4*)(k + ((size_t)(kt*64+key)*B_ + b)*kvS
                                            + col0 + 4*c);
            float hx = __bfloat162float(__float2bfloat16_rn(kv4.x));
            float hy = __bfloat162float(__float2bfloat16_rn(kv4.y));
            float hz = __bfloat162float(__float2bfloat16_rn(kv4.z));
            float hw = __bfloat162float(__float2bfloat16_rn(kv4.w));
            Ks[key][2*c  ] = pack_bf2(hx, hy);
            Ks[key][2*c+1] = pack_bf2(hz, hw);
            Ks[key][32 + 2*c  ] = pack_bf2(kv4.x - hx, kv4.y - hy);
            Ks[key][32 + 2*c+1] = pack_bf2(kv4.z - hz, kv4.w - hw);
        }
        #pragma unroll
        for (int it = 0; it < 4; it++) {
            int idx = t + 256*it;
            int j = idx >> 5;
            int d = idx & 31;
            const float* vp0 = v + ((size_t)(kt*64 + 2*j)*B_ + b)*kvS + col0 + 2*d;
            float2 va = *(const float2*)vp0;
            float2 vb = *(const float2*)(vp0 + (size_t)B_*kvS);
            float hax = __bfloat162float(__float2bfloat16_rn(va.x));
            float hay = __bfloat162float(__float2bfloat16_rn(va.y));
            float hbx = __bfloat162float(__float2bfloat16_rn(vb.x));
            float hby = __bfloat162float(__float2bfloat16_rn(vb.y));
            Vt[2*d  ][j] = pack_bf2(hax, hbx);
            Vt[2*d+1][j] = pack_bf2(hay, hby);
            Vt[2*d  ][32 + j] = pack_bf2(va.x - hax, vb.x - hbx);
            Vt[2*d+1][32 + j] = pack_bf2(va.y - hay, vb.y - hby);
        }
        __syncthreads();

        float sc[8][4];
        #pragma unroll
        for (int i = 0; i < 8; i++)
            #pragma unroll
            for (int j = 0; j < 4; j++) sc[i][j] = 0.f;
        // term-major QK^T: hi*hi, hi*lo, lo*hi (8 independent accs between reuses)
        #pragma unroll
        for (int ks = 0; ks < 4; ks++)
            #pragma unroll
            for (int ni = 0; ni < 8; ni++) {
                int nr = ni*8 + r0;
                mma16816(sc[ni], qh[ks], Ks[nr][cq + 8*ks], Ks[nr][cq + 8*ks + 4]);
            }
        #pragma unroll
        for (int ks = 0; ks < 4; ks++)
            #pragma unroll
            for (int ni = 0; ni < 8; ni++) {
                int nr = ni*8 + r0;
                mma16816(sc[ni], qh[ks], Ks[nr][32 + cq + 8*ks],
                         Ks[nr][32 + cq + 8*ks + 4]);
            }
        #pragma unroll
        for (int ks = 0; ks < 4; ks++)
            #pragma unroll
            for (int ni = 0; ni < 8; ni++) {
                int nr = ni*8 + r0;
                mma16816(sc[ni], ql[ks], Ks[nr][cq + 8*ks], Ks[nr][cq + 8*ks + 4]);
            }

        const float scale = 0.125f;
        bool diag = (kt >= 2*qt);
        int rg0 = qrow + r0, rg8 = rg0 + 8;
        float tm0 = -3.4e38f, tm8 = -3.4e38f;
        #pragma unroll
        for (int ni = 0; ni < 8; ni++) {
            float s0 = sc[ni][0]*scale, s1 = sc[ni][1]*scale;
            float s2 = sc[ni][2]*scale, s3 = sc[ni][3]*scale;
            if (diag) {
                int colg = kt*64 + ni*8 + 2*cq;
                if (colg     > rg0) s0 = -3.4e38f;
                if (colg + 1 > rg0) s1 = -3.4e38f;
                if (colg     > rg8) s2 = -3.4e38f;
                if (colg + 1 > rg8) s3 = -3.4e38f;
            }
            sc[ni][0] = s0; sc[ni][1] = s1; sc[ni][2] = s2; sc[ni][3] = s3;
            tm0 = fmaxf(tm0, fmaxf(s0, s1));
            tm8 = fmaxf(tm8, fmaxf(s2, s3));
        }
        tm0 = fmaxf(tm0, __shfl_xor_sync(0xffffffff, tm0, 1));
        tm0 = fmaxf(tm0, __shfl_xor_sync(0xffffffff, tm0, 2));
        tm8 = fmaxf(tm8, __shfl_xor_sync(0xffffffff, tm8, 1));
        tm8 = fmaxf(tm8, __shfl_xor_sync(0xffffffff, tm8, 2));
        float mn0 = fmaxf(m0, tm0), mn8 = fmaxf(m8, tm8);
        float al0 = __expf(m0 - mn0), al8 = __expf(m8 - mn8);
        m0 = mn0; m8 = mn8;
        float rs0 = 0.f, rs8 = 0.f;
        #pragma unroll
        for (int ni = 0; ni < 8; ni++) {
            float p0 = __expf(sc[ni][0] - mn0);
            float p1 = __expf(sc[ni][1] - mn0);
            float p2 = __expf(sc[ni][2] - mn8);
            float p3 = __expf(sc[ni][3] - mn8);
            sc[ni][0] = p0; sc[ni][1] = p1; sc[ni][2] = p2; sc[ni][3] = p3;
            rs0 += p0 + p1; rs8 += p2 + p3;
        }
        rs0 += __shfl_xor_sync(0xffffffff, rs0, 1);
        rs0 += __shfl_xor_sync(0xffffffff, rs0, 2);
        rs8 += __shfl_xor_sync(0xffffffff, rs8, 1);
        rs8 += __shfl_xor_sync(0xffffffff, rs8, 2);
        l0 = l0*al0 + rs0;
        l8 = l8*al8 + rs8;
        #pragma unroll
        for (int ni = 0; ni < 8; ni++) {
            Oc[ni][0] *= al0; Oc[ni][1] *= al0;
            Oc[ni][2] *= al8; Oc[ni][3] *= al8;
        }

        uint32_t ph[4][4], pl[4][4];
        #pragma unroll
        for (int ks2 = 0; ks2 < 4; ks2++) {
            float x0 = sc[2*ks2][0],   x1 = sc[2*ks2][1];
            float x2 = sc[2*ks2][2],   x3 = sc[2*ks2][3];
            float y0 = sc[2*ks2+1][0], y1 = sc[2*ks2+1][1];
            float y2 = sc[2*ks2+1][2], y3 = sc[2*ks2+1][3];
            float hx0 = __bfloat162float(__float2bfloat16_rn(x0));
            float hx1 = __bfloat162float(__float2bfloat16_rn(x1));
            float hx2 = __bfloat162float(__float2bfloat16_rn(x2));
            float hx3 = __bfloat162float(__float2bfloat16_rn(x3));
            float hy0 = __bfloat162float(__float2bfloat16_rn(y0));
            float hy1 = __bfloat162float(__float2bfloat16_rn(y1));
            float hy2 = __bfloat162float(__float2bfloat16_rn(y2));
            float hy3 = __bfloat162float(__float2bfloat16_rn(y3));
            ph[ks2][0] = pack_bf2(hx0, hx1);
            ph[ks2][1] = pack_bf2(hx2, hx3);
            ph[ks2][2] = pack_bf2(hy0, hy1);
            ph[ks2][3] = pack_bf2(hy2, hy3);
            pl[ks2][0] = pack_bf2(x0 - hx0, x1 - hx1);
            pl[ks2][1] = pack_bf2(x2 - hx2, x3 - hx3);
            pl[ks2][2] = pack_bf2(y0 - hy0, y1 - hy1);
            pl[ks2][3] = pack_bf2(y2 - hy2, y3 - hy3);
        }

        // term-major PV
        #pragma unroll
        for (int ks2 = 0; ks2 < 4; ks2++)
            #pragma unroll
            for (int ni = 0; ni < 8; ni++) {
                int nr = ni*8 + r0;
                mma16816(Oc[ni], ph[ks2], Vt[nr][cq + 8*ks2], Vt[nr][cq + 8*ks2 + 4]);
            }
        #pragma unroll
        for (int ks2 = 0; ks2 < 4; ks2++)
            #pragma unroll
            for (int ni = 0; ni < 8; ni++) {
                int nr = ni*8 + r0;
                mma16816(Oc[ni], ph[ks2], Vt[nr][32 + cq + 8*ks2],
                         Vt[nr][32 + cq + 8*ks2 + 4]);
            }
        #pragma unroll
        for (int ks2 = 0; ks2 < 4; ks2++)
            #pragma unroll
            for (int ni = 0; ni < 8; ni++) {
                int nr = ni*8 + r0;
                mma16816(Oc[ni], pl[ks2], Vt[nr][cq + 8*ks2], Vt[nr][cq + 8*ks2 + 4]);
            }
        __syncthreads();
    }

    float i0 = 1.f / l0, i8 = 1.f / l8;
    #pragma unroll
    for (int ni = 0; ni < 8; ni++) {
        int cc = col0 + ni*8 + 2*cq;
        float2 w0 = {Oc[ni][0]*i0, Oc[ni][1]*i0};
        float2 w8 = {Oc[ni][2]*i8, Oc[ni][3]*i8};
        *(float2*)(o + ((size_t)(qrow + r0    )*B_ + b)*oS + cc) = w0;
        *(float2*)(o + ((size_t)(qrow + r0 + 8)*B_ + b)*oS + cc) = w8;
    }
}

// -------- memory retrieval + delta + fused gated combine ----------------------
__global__ __launch_bounds__(256) void mem_retrieve(
    const float* __restrict__ q, const float* __restrict__ kp,
    const float* __restrict__ vp, const float* __restrict__ memory,
    const float* __restrict__ mem_norm, int l,
    const float* __restrict__ attn, float gate,
    float* __restrict__ content, float* __restrict__ diff, float* __restrict__ cKout,
    int qS, int kvS)
{
    int bn = blockIdx.x;
    int b = bn / NH_, n = bn % NH_;
    int chunk = blockIdx.y;
    int t = threadIdx.x;

    __shared__ float Msh[DH_][DH_+1];
    __shared__ float normsh[DH_];
    __shared__ float cqsh[4][DH_];
    __shared__ float cksh[4][DH_];

    const float* Mg = memory + ((size_t)(l*B_ + b)*NH_ + n)*DH_*DH_;
    for (int idx = t; idx < DH_*DH_; idx += 256) Msh[idx >> 6][idx & 63] = Mg[idx];
    if (t < DH_) normsh[t] = mem_norm[((size_t)(l*B_ + b)*NH_ + n)*DH_ + t];
    __syncthreads();

    int g = t >> 6, d = t & 63;
    int col = n * DH_;
    for (int it = 0; it < 32; ++it) {
        int s = chunk*128 + it*4 + g;
        size_t row = (size_t)(s*B_ + b);
        float qvl = q [row*qS  + col + d];
        float vvl = vp[row*kvS + col + d];
        float cq = qvl > 0.f ? qvl + 1.f : __expf(qvl);
        float ck = vvl > 0.f ? vvl + 1.f : __expf(vvl);
        cqsh[g][d] = cq; cksh[g][d] = ck;
        __syncthreads();
        float accA = 0.f, accB = 0.f, denQ = 0.f, denK = 0.f;
        #pragma unroll 8
        for (int kk = 0; kk < DH_; kk++) {
            float mq = Msh[kk][d];
            accA += cqsh[g][kk] * mq;
            accB += cksh[g][kk] * mq;
            denQ += cqsh[g][kk] * normsh[kk];
            denK += cksh[g][kk] * normsh[kk];
        }
        size_t oidx = row*D_ + col + d;
        content[oidx] = gate * (accA / denQ) + (1.f - gate) * attn[oidx];
        diff[oidx]    = kp[row*kvS + col + d] - accB / denK;
        cKout[oidx]   = ck;
        __syncthreads();
    }
}

// -------- memory update: newM[k][v] = M[k][v] + sum_s cK[s,k]*diff[s,v] ------
__global__ __launch_bounds__(256) void mem_update(
    const float* __restrict__ cK, const float* __restrict__ diff,
    const float* __restrict__ memory, int l, float* __restrict__ outM)
{
    int bn = blockIdx.x;
    int b = bn / NH_, n = bn % NH_;
    __shared__ float aS[16][DH_];
    __shared__ float bS[16][DH_];
    int t = threadIdx.x;
    int tx = t & 15, ty = t >> 4;
    float acc[4][4] = {};
    int col = n * DH_;
    int r  = t >> 4;
    int c4 = (t & 15) * 4;
    for (int s0 = 0; s0 < S_; s0 += 16) {
        size_t row = (size_t)((s0 + r)*B_ + b);
        *(float4*)&aS[r][c4] = *(const float4*)(cK   + row*D_ + col + c4);
        *(float4*)&bS[r][c4] = *(const float4*)(diff + row*D_ + col + c4);
        __syncthreads();
        #pragma unroll
        for (int ss = 0; ss < 16; ss++) {
            float a[4], bb[4];
            #pragma unroll
            for (int u = 0; u < 4; u++) { a[u] = aS[ss][ty*4+u]; bb[u] = bS[ss][tx*4+u]; }
            #pragma unroll
            for (int i = 0; i < 4; i++)
                #pragma unroll
                for (int j = 0; j < 4; j++)
                    acc[i][j] = fmaf(a[i], bb[j], acc[i][j]);
        }
        __syncthreads();
    }
    const float* Mg = memory + ((size_t)(l*B_ + b)*NH_ + n)*DH_*DH_;
    float*       Og = outM   + ((size_t)(l*B_ + b)*NH_ + n)*DH_*DH_;
    #pragma unroll
    for (int i = 0; i < 4; i++)
        #pragma unroll
        for (int j = 0; j < 4; j++) {
            int kk = ty*4 + i, vv = tx*4 + j;
            Og[kk*DH_ + vv] = Mg[kk*DH_ + vv] + acc[i][j];
        }
}

// -------- norm update: outN = mem_norm + sum_s cK (parallel over s) ----------
__global__ __launch_bounds__(512) void norm_update(
    const float* __restrict__ cK, const float* __restrict__ mem_norm, int l,
    float* __restrict__ outN)
{
    int bn = blockIdx.x;
    int b = bn / NH_, n = bn % NH_;
    int t = threadIdx.x;
    int d = t & 63, sg = t >> 6;
    int col = n * DH_;
    float acc = 0.f;
    for (int s = sg; s < S_; s += 8)
        acc += cK[(size_t)(s*B_ + b)*D_ + col + d];
    __shared__ float red[512];
    red[t] = acc; __syncthreads();
    if (t < 256) red[t] += red[t + 256]; __syncthreads();
    if (t < 128) red[t] += red[t + 128]; __syncthreads();
    if (t < 64) {
        size_t o = ((size_t)(l*B_ + b)*NH_ + n)*DH_ + t;
        outN[o] = mem_norm[o] + red[t] + red[t + 64];
    }
}

// -------- layernorm with residual: out = LN(res + y) --------------------------
__global__ __launch_bounds__(256) void ln_kernel(
    const float* __restrict__ res, const float* __restrict__ y,
    const float* __restrict__ g, const float* __restrict__ bb,
    float* __restrict__ out)
{
    int row = blockIdx.x;
    int t = threadIdx.x;
    __shared__ float red[256];
    size_t base = (size_t)row * D_;
    float x0 = res[base + t      ] + y[base + t      ];
    float x1 = res[base + t + 256] + y[base + t + 256];
    float x2 = res[base + t + 512] + y[base + t + 512];
    red[t] = x0 + x1 + x2; __syncthreads();
    for (int o = 128; o > 0; o >>= 1) { if (t < o) red[t] += red[t+o]; __syncthreads(); }
    float mu = red[0] * (1.f / 768.f); __syncthreads();
    float d0 = x0 - mu, d1 = x1 - mu, d2 = x2 - mu;
    red[t] = d0*d0 + d1*d1 + d2*d2; __syncthreads();
    for (int o = 128; o > 0; o >>= 1) { if (t < o) red[t] += red[t+o]; __syncthreads(); }
    float inv = rsqrtf(red[0] * (1.f / 768.f) + 1e-5f);
    out[base + t      ] = d0 * inv * g[t      ] + bb[t      ];
    out[base + t + 256] = d1 * inv * g[t + 256] + bb[t + 256];
    out[base + t + 512] = d2 * inv * g[t + 512] + bb[t + 512];
}

// ------------------------------- launcher -------------------------------------
extern "C" void kernel_launch(void* const* d_in, const int* in_sizes, int n_in,
                              void* d_out, int out_size)
{
    const int*   inp      = (const int*)  d_in[0];
    const float* word_emb = (const float*)d_in[1];
    const float* Wq       = (const float*)d_in[2];
    const float* Wkv      = (const float*)d_in[3];
    const float* Wo       = (const float*)d_in[4];
    const float* ln1g     = (const float*)d_in[5];
    const float* ln1b     = (const float*)d_in[6];
    const float* ffW1     = (const float*)d_in[7];
    const float* ffb1     = (const float*)d_in[8];
    const float* ffW2     = (const float*)d_in[9];
    const float* ffb2     = (const float*)d_in[10];
    const float* ln2g     = (const float*)d_in[11];
    const float* ln2b     = (const float*)d_in[12];
    const float* memory   = (const float*)d_in[13];
    const float* mem_norm = (const float*)d_in[14];

    float* out  = (float*)d_out;
    float* outH = out;                         // (S,B,D)
    float* outM = out + (size_t)SB_*D_;        // (L,B,NH,DH,DH)
    float* outN = outM + (size_t)L_*B_*NH_*DH_*DH_;  // (L,B,NH,DH)

    float *h, *q, *kv, *attn, *content, *cK, *diff, *ff, *out1;
    cudaGetSymbolAddress((void**)&h,       g_h);
    cudaGetSymbolAddress((void**)&q,       g_q);
    cudaGetSymbolAddress((void**)&kv,      g_kv);
    cudaGetSymbolAddress((void**)&attn,    g_attn);
    cudaGetSymbolAddress((void**)&content, g_content);
    cudaGetSymbolAddress((void**)&cK,      g_cK);
    cudaGetSymbolAddress((void**)&diff,    g_diff);
    cudaGetSymbolAddress((void**)&ff,      g_ff);
    cudaGetSymbolAddress((void**)&out1,    g_out1);

    const float gate = 1.0f / (1.0f + expf(-0.01f));

    embed_kernel<<<SB_, 256>>>(inp, word_emb, h);

    for (int l = 0; l < L_; l++) {
        // q = h @ Wq^T   (4096 x 768 x 768)
        gemm_bf16s<<<dim3(D_/128, SB_/128), 256>>>(h, Wq + (size_t)l*D_*D_, nullptr, q,
                                                   SB_, D_, D_, 0);
        // kv = h @ Wkv^T (4096 x 1536 x 768)
        gemm_bf16s<<<dim3(2*D_/128, SB_/128), 256>>>(h, Wkv + (size_t)l*2*D_*D_, nullptr, kv,
                                                     SB_, 2*D_, D_, 0);
        // local causal attention (tensor-core flash, 128 queries per block)
        attn_mma<<<dim3(8, B_*NH_), 256>>>(q, kv /*k*/, kv + D_ /*v*/, attn,
                                           D_, 2*D_, D_);
        // memory retrieval + delta + fused gated combine (content = gated mix)
        mem_retrieve<<<dim3(B_*NH_, 8), 256>>>(q, kv /*k*/, kv + D_ /*v*/,
                                               memory, mem_norm, l,
                                               attn, gate,
                                               content, diff, cK, D_, 2*D_);
        // memory + norm updates straight into d_out
        mem_update<<<B_*NH_, 256>>>(cK, diff, memory, l, outM);
        norm_update<<<B_*NH_, 512>>>(cK, mem_norm, l, outN);
        // Wo projection (content holds the gated attention mix; write into attn)
        gemm_bf16s<<<dim3(D_/128, SB_/128), 256>>>(content, Wo + (size_t)l*D_*D_, nullptr, attn,
                                                   SB_, D_, D_, 0);
        // ln1: out1 = LN(h + proj)
        ln_kernel<<<SB_, 256>>>(h, attn, ln1g + l*D_, ln1b + l*D_, out1);
        // ff1 = relu(out1 @ W1^T + b1)  (4096 x 3072 x 768)
        gemm_bf16s<<<dim3(DI_/128, SB_/128), 256>>>(out1, ffW1 + (size_t)l*DI_*D_, ffb1 + l*DI_,
                                                    ff, SB_, DI_, D_, 1);
        // ff2 = ff1 @ W2^T + b2         (4096 x 768 x 3072)
        gemm_bf16s<<<dim3(D_/128, SB_/128), 256>>>(ff, ffW2 + (size_t)l*D_*DI_, ffb2 + l*D_,
                                                   content, SB_, D_, DI_, 2);
        // ln2: h = LN(out1 + ff2)
        ln_kernel<<<SB_, 256>>>(out1, content, ln2g + l*D_, ln2b + l*D_, h);
    }

    cudaMemcpyAsync(outH, h, (size_t)SB_*D_*sizeof(float),
                    cudaMemcpyDeviceToDevice);
}

// round 9
// speedup vs baseline: 4.1990x; 1.0843x over previous
#include <cuda_runtime.h>
#include <cuda_bf16.h>
#include <math.h>
#include <stdint.h>

// Problem dims
#define S_  1024
#define B_  4
#define D_  768
#define NH_ 12
#define DH_ 64
#define L_  4
#define DI_ 3072
#define SB_ (S_*B_)

// ---------------- scratch (device globals; no allocation allowed) ------------
__device__ float g_h[SB_*D_];
__device__ float g_q[SB_*D_];
__device__ float g_kv[SB_*2*D_];
__device__ float g_attn[SB_*D_];
__device__ float g_content[SB_*D_];
__device__ float g_cK[SB_*D_];
__device__ float g_diff[SB_*D_];
__device__ float g_ff[SB_*DI_];
__device__ float g_out1[SB_*D_];
__device__ float g_wo[SB_*D_];

// pack two floats into bf16x2 (lo half = first arg)
__device__ __forceinline__ uint32_t pack_bf2(float a, float b) {
    __nv_bfloat162 h = __floats2bfloat162_rn(a, b);
    return *(uint32_t*)&h;
}

__device__ __forceinline__ void mma16816(float* d, const uint32_t* a,
                                         uint32_t b0, uint32_t b1) {
    asm volatile(
        "mma.sync.aligned.m16n8k16.row.col.f32.bf16.bf16.f32 "
        "{%0,%1,%2,%3}, {%4,%5,%6,%7}, {%8,%9}, {%0,%1,%2,%3};"
        : "+f"(d[0]), "+f"(d[1]), "+f"(d[2]), "+f"(d[3])
        : "r"(a[0]), "r"(a[1]), "r"(a[2]), "r"(a[3]), "r"(b0), "r"(b1));
}

// ---------------- embedding + sinusoidal positional encoding -----------------
__global__ void embed_kernel(const int* __restrict__ inp,
                             const float* __restrict__ we,
                             float* __restrict__ h)
{
    int row = blockIdx.x;          // row = s*B + b
    int s = row / B_;
    int b = row % B_;
    int t = threadIdx.x;           // 256
    int tok = inp[s*B_ + b];
    float pos = (float)(S_ - 1 - s);
    const float lg = logf(10000.0f);
    for (int d = t; d < D_; d += 256) {
        int i = (d < 384) ? d : d - 384;
        float freq = expf(-((float)(2*i) / (float)D_) * lg);
        float ang = pos * freq;
        float pe = (d < 384) ? sinf(ang) : cosf(ang);
        h[(size_t)row*D_ + d] = we[(size_t)tok*D_ + d] * 27.712812921102035f + pe;
    }
}

// ---------------- NT GEMM body (bf16 tensor cores, hi/lo split = ~fp32) ------
// C[M,N] = A[M,K] @ B[N,K]^T. 128x128 tile, KT=16, 8 warps, term-major mma.
// FUSE: A := gate*A + (1-gate)*A2 elementwise at load.
// epi: 0 = none, 1 = bias+relu, 2 = bias
#define KT 16
#define KP 20
template <bool FUSE>
__device__ __forceinline__ void gemm_body(
    const float* __restrict__ A, const float* __restrict__ A2, float gate,
    const float* __restrict__ Bm, const float* __restrict__ bias,
    float* __restrict__ C, int N, int K, int epi, int m0, int n0)
{
    __shared__ __align__(16) uint32_t As[2][128][KP];
    __shared__ __align__(16) uint32_t Bs[2][128][KP];
    int tid  = threadIdx.x;
    int warp = tid >> 5, lane = tid & 31;
    int wm = warp >> 2, wn = warp & 3;        // 2 x 4 warp grid
    int r0 = lane >> 2, cq = lane & 3;

    int lr = tid >> 2;          // 0..63
    int lc = (tid & 3) * 4;     // 0,4,8,12 (k offset in floats)
    int wc = lc >> 1;           // word col: 0,2,4,6
    const float* Ap  = A  + (size_t)(m0 + lr)*K + lc;
    const float* A2p = FUSE ? (A2 + (size_t)(m0 + lr)*K + lc) : nullptr;
    const float* Bp  = Bm + (size_t)(n0 + lr)*K + lc;

    float acc[16][4];
    #pragma unroll
    for (int i = 0; i < 16; i++)
        #pragma unroll
        for (int j = 0; j < 4; j++) acc[i][j] = 0.f;

    #define LOAD_A(off)                                                        \
        ({ float4 _a = *(const float4*)(Ap + (off));                           \
           if (FUSE) { float4 _b = *(const float4*)(A2p + (off));              \
               _a.x = gate*_a.x + (1.f-gate)*_b.x;                              \
               _a.y = gate*_a.y + (1.f-gate)*_b.y;                              \
               _a.z = gate*_a.z + (1.f-gate)*_b.z;                              \
               _a.w = gate*_a.w + (1.f-gate)*_b.w; }                            \
           _a; })

    #define STORE_SPLIT(dst, row, vec)                                          \
    {                                                                           \
        float4 _v = (vec);                                                      \
        float hx = __bfloat162float(__float2bfloat16_rn(_v.x));                 \
        float hy = __bfloat162float(__float2bfloat16_rn(_v.y));                 \
        float hz = __bfloat162float(__float2bfloat16_rn(_v.z));                 \
        float hw = __bfloat162float(__float2bfloat16_rn(_v.w));                 \
        dst[row][wc+0] = pack_bf2(hx, hy);                                      \
        dst[row][wc+1] = pack_bf2(hz, hw);                                      \
        dst[row][8+wc+0] = pack_bf2(_v.x - hx, _v.y - hy);                      \
        dst[row][8+wc+1] = pack_bf2(_v.z - hz, _v.w - hw);                      \
    }

    {
        float4 a0v = LOAD_A(0);
        float4 a1v = LOAD_A((size_t)64*K);
        float4 b0v = *(const float4*)Bp;
        float4 b1v = *(const float4*)(Bp + (size_t)64*K);
        STORE_SPLIT(As[0], lr,      a0v);
        STORE_SPLIT(As[0], lr + 64, a1v);
        STORE_SPLIT(Bs[0], lr,      b0v);
        STORE_SPLIT(Bs[0], lr + 64, b1v);
    }
    __syncthreads();

    int buf = 0;
    for (int k0 = KT; k0 < K + KT; k0 += KT) {
        bool more = (k0 < K);
        float4 a0v, a1v, b0v, b1v;
        if (more) {
            a0v = LOAD_A(k0);
            a1v = LOAD_A((size_t)64*K + k0);
            b0v = *(const float4*)(Bp + k0);
            b1v = *(const float4*)(Bp + (size_t)64*K + k0);
        }
        uint32_t ah[4][4], al[4][4], bh[4][2], bl[4][2];
        #pragma unroll
        for (int mi = 0; mi < 4; mi++) {
            int mr = wm*64 + mi*16 + r0;
            ah[mi][0] = As[buf][mr    ][cq];
            ah[mi][1] = As[buf][mr + 8][cq];
            ah[mi][2] = As[buf][mr    ][cq + 4];
            ah[mi][3] = As[buf][mr + 8][cq + 4];
            al[mi][0] = As[buf][mr    ][8 + cq];
            al[mi][1] = As[buf][mr + 8][8 + cq];
            al[mi][2] = As[buf][mr    ][8 + cq + 4];
            al[mi][3] = As[buf][mr + 8][8 + cq + 4];
        }
        #pragma unroll
        for (int ni = 0; ni < 4; ni++) {
            int nr = wn*32 + ni*8 + r0;
            bh[ni][0] = Bs[buf][nr][cq];
            bh[ni][1] = Bs[buf][nr][cq + 4];
            bl[ni][0] = Bs[buf][nr][8 + cq];
            bl[ni][1] = Bs[buf][nr][8 + cq + 4];
        }
        #pragma unroll
        for (int mi = 0; mi < 4; mi++)
            #pragma unroll
            for (int ni = 0; ni < 4; ni++)
                mma16816(acc[mi*4 + ni], ah[mi], bh[ni][0], bh[ni][1]);
        #pragma unroll
        for (int mi = 0; mi < 4; mi++)
            #pragma unroll
            for (int ni = 0; ni < 4; ni++)
                mma16816(acc[mi*4 + ni], ah[mi], bl[ni][0], bl[ni][1]);
        #pragma unroll
        for (int mi = 0; mi < 4; mi++)
            #pragma unroll
            for (int ni = 0; ni < 4; ni++)
                mma16816(acc[mi*4 + ni], al[mi], bh[ni][0], bh[ni][1]);
        if (more) {
            int nb = buf ^ 1;
            STORE_SPLIT(As[nb], lr,      a0v);
            STORE_SPLIT(As[nb], lr + 64, a1v);
            STORE_SPLIT(Bs[nb], lr,      b0v);
            STORE_SPLIT(Bs[nb], lr + 64, b1v);
            __syncthreads();
            buf = nb;
        }
    }
    #undef STORE_SPLIT
    #undef LOAD_A

    #pragma unroll
    for (int mi = 0; mi < 4; mi++) {
        int m = m0 + wm*64 + mi*16 + r0;
        #pragma unroll
        for (int ni = 0; ni < 4; ni++) {
            int n = n0 + wn*32 + ni*8 + 2*cq;
            float* d = acc[mi*4 + ni];
            float2 v0 = {d[0], d[1]};
            float2 v1 = {d[2], d[3]};
            if (epi == 1) {
                float b0v = bias[n], b1v = bias[n+1];
                v0.x = fmaxf(v0.x + b0v, 0.f); v0.y = fmaxf(v0.y + b1v, 0.f);
                v1.x = fmaxf(v1.x + b0v, 0.f); v1.y = fmaxf(v1.y + b1v, 0.f);
            } else if (epi == 2) {
                float b0v = bias[n], b1v = bias[n+1];
                v0.x += b0v; v0.y += b1v;
                v1.x += b0v; v1.y += b1v;
            }
            *(float2*)(C + (size_t)m*N + n)       = v0;
            *(float2*)(C + (size_t)(m+8)*N + n)   = v1;
        }
    }
}

__global__ __launch_bounds__(256) void gemm_bf16s(
    const float* __restrict__ A, const float* __restrict__ Bm,
    const float* __restrict__ bias, float* __restrict__ C,
    int N, int K, int epi)
{
    gemm_body<false>(A, nullptr, 0.f, Bm, bias, C, N, K, epi,
                     blockIdx.y*128, blockIdx.x*128);
}

// fused combine GEMM: C = (gate*A + (1-gate)*A2) @ B^T
__global__ __launch_bounds__(256) void gemm_wo(
    const float* __restrict__ A, const float* __restrict__ A2, float gate,
    const float* __restrict__ Bm, float* __restrict__ C, int N, int K)
{
    gemm_body<true>(A, A2, gate, Bm, nullptr, C, N, K, 0,
                    blockIdx.y*128, blockIdx.x*128);
}

// merged Q + KV projection: blocks 0..5 -> q, 6..17 -> kv
__global__ __launch_bounds__(256) void gemm_qkv(
    const float* __restrict__ A, const float* __restrict__ Wq,
    const float* __restrict__ Wkv, float* __restrict__ q,
    float* __restrict__ kv, int K)
{
    int bx = blockIdx.x, m0 = blockIdx.y*128;
    if (bx < 6)
        gemm_body<false>(A, nullptr, 0.f, Wq,  nullptr, q,  D_,   K, 0, m0, bx*128);
    else
        gemm_body<false>(A, nullptr, 0.f, Wkv, nullptr, kv, 2*D_, K, 0, m0, (bx-6)*128);
}

// ------------- tensor-core flash attention (bf16 hi/lo, fp32 acc) -------------
__global__ __launch_bounds__(256) void attn_mma(
    const float* __restrict__ q, const float* __restrict__ k,
    const float* __restrict__ v, float* __restrict__ o,
    int qS, int kvS, int oS)
{
    int qt = 7 - (int)blockIdx.x;          // big-work blocks first
    int bn = blockIdx.y;
    int b = bn / NH_, n = bn % NH_;
    int col0 = n * DH_;
    int t = threadIdx.x, lane = t & 31, warp = t >> 5;
    int r0 = lane >> 2, cq = lane & 3;

    __shared__ __align__(16) uint32_t Ks[64][68];
    __shared__ __align__(16) uint32_t Vt[64][68];

    int qrow = qt*128 + warp*16;

    uint32_t qh[4][4], ql[4][4];
    #pragma unroll
    for (int ks = 0; ks < 4; ks++) {
        int cb = ks*16 + 2*cq;
        #pragma unroll
        for (int u = 0; u < 4; u++) {
            int rr = qrow + r0 + ((u & 1) ? 8 : 0);
            int cc = cb + ((u & 2) ? 8 : 0);
            float2 qv = *(const float2*)(q + ((size_t)rr*B_ + b)*qS + col0 + cc);
            float hx = __bfloat162float(__float2bfloat16_rn(qv.x));
            float hy = __bfloat162float(__float2bfloat16_rn(qv.y));
            qh[ks][u] = pack_bf2(hx, hy);
            ql[ks][u] = pack_bf2(qv.x - hx, qv.y - hy);
        }
    }

    float Oc[8][4];
    #pragma unroll
    for (int i = 0; i < 8; i++)
        #pragma unroll
        for (int j = 0; j < 4; j++) Oc[i][j] = 0.f;
    float m0 = -3.4e38f, m8 = -3.4e38f, l0 = 0.f, l8 = 0.f;

    int nkt = 2*qt + 2;
    for (int kt = 0; kt < nkt; kt++) {
        for (int idx = t; idx < 64*16; idx += 256) {
            int key = idx >> 4, c = idx & 15;
            float4 kv4 = *(const float4*)(k + ((size_t)(kt*64+key)*B_ + b)*kvS
                                            + col0 + 4*c);
            float hx = __bfloat162float(__float2bfloat16_rn(kv4.x));
            float hy = __bfloat162float(__float2bfloat16_rn(kv4.y));
            float hz = __bfloat162float(__float2bfloat16_rn(kv4.z));
            float hw = __bfloat162float(__float2bfloat16_rn(kv4.w));
            Ks[key][2*c  ] = pack_bf2(hx, hy);
            Ks[key][2*c+1] = pack_bf2(hz, hw);
            Ks[key][32 + 2*c  ] = pack_bf2(kv4.x - hx, kv4.y - hy);
            Ks[key][32 + 2*c+1] = pack_bf2(kv4.z - hz, kv4.w - hw);
        }
        #pragma unroll
        for (int it = 0; it < 4; it++) {
            int idx = t + 256*it;
            int j = idx >> 5;
            int d = idx & 31;
            const float* vp0 = v + ((size_t)(kt*64 + 2*j)*B_ + b)*kvS + col0 + 2*d;
            float2 va = *(const float2*)vp0;
            float2 vb = *(const float2*)(vp0 + (size_t)B_*kvS);
            float hax = __bfloat162float(__float2bfloat16_rn(va.x));
            float hay = __bfloat162float(__float2bfloat16_rn(va.y));
            float hbx = __bfloat162float(__float2bfloat16_rn(vb.x));
            float hby = __bfloat162float(__float2bfloat16_rn(vb.y));
            Vt[2*d  ][j] = pack_bf2(hax, hbx);
            Vt[2*d+1][j] = pack_bf2(hay, hby);
            Vt[2*d  ][32 + j] = pack_bf2(va.x - hax, vb.x - hbx);
            Vt[2*d+1][32 + j] = pack_bf2(va.y - hay, vb.y - hby);
        }
        __syncthreads();

        float sc[8][4];
        #pragma unroll
        for (int i = 0; i < 8; i++)
            #pragma unroll
            for (int j = 0; j < 4; j++) sc[i][j] = 0.f;
        #pragma unroll
        for (int ks = 0; ks < 4; ks++)
            #pragma unroll
            for (int ni = 0; ni < 8; ni++) {
                int nr = ni*8 + r0;
                mma16816(sc[ni], qh[ks], Ks[nr][cq + 8*ks], Ks[nr][cq + 8*ks + 4]);
            }
        #pragma unroll
        for (int ks = 0; ks < 4; ks++)
            #pragma unroll
            for (int ni = 0; ni < 8; ni++) {
                int nr = ni*8 + r0;
                mma16816(sc[ni], qh[ks], Ks[nr][32 + cq + 8*ks],
                         Ks[nr][32 + cq + 8*ks + 4]);
            }
        #pragma unroll
        for (int ks = 0; ks < 4; ks++)
            #pragma unroll
            for (int ni = 0; ni < 8; ni++) {
                int nr = ni*8 + r0;
                mma16816(sc[ni], ql[ks], Ks[nr][cq + 8*ks], Ks[nr][cq + 8*ks + 4]);
            }

        const float scale = 0.125f;
        bool diag = (kt >= 2*qt);
        int rg0 = qrow + r0, rg8 = rg0 + 8;
        float tm0 = -3.4e38f, tm8 = -3.4e38f;
        #pragma unroll
        for (int ni = 0; ni < 8; ni++) {
            float s0 = sc[ni][0]*scale, s1 = sc[ni][1]*scale;
            float s2 = sc[ni][2]*scale, s3 = sc[ni][3]*scale;
            if (diag) {
                int colg = kt*64 + ni*8 + 2*cq;
                if (colg     > rg0) s0 = -3.4e38f;
                if (colg + 1 > rg0) s1 = -3.4e38f;
                if (colg     > rg8) s2 = -3.4e38f;
                if (colg + 1 > rg8) s3 = -3.4e38f;
            }
            sc[ni][0] = s0; sc[ni][1] = s1; sc[ni][2] = s2; sc[ni][3] = s3;
            tm0 = fmaxf(tm0, fmaxf(s0, s1));
            tm8 = fmaxf(tm8, fmaxf(s2, s3));
        }
        tm0 = fmaxf(tm0, __shfl_xor_sync(0xffffffff, tm0, 1));
        tm0 = fmaxf(tm0, __shfl_xor_sync(0xffffffff, tm0, 2));
        tm8 = fmaxf(tm8, __shfl_xor_sync(0xffffffff, tm8, 1));
        tm8 = fmaxf(tm8, __shfl_xor_sync(0xffffffff, tm8, 2));
        float mn0 = fmaxf(m0, tm0), mn8 = fmaxf(m8, tm8);
        float al0 = __expf(m0 - mn0), al8 = __expf(m8 - mn8);
        m0 = mn0; m8 = mn8;
        float rs0 = 0.f, rs8 = 0.f;
        #pragma unroll
        for (int ni = 0; ni < 8; ni++) {
            float p0 = __expf(sc[ni][0] - mn0);
            float p1 = __expf(sc[ni][1] - mn0);
            float p2 = __expf(sc[ni][2] - mn8);
            float p3 = __expf(sc[ni][3] - mn8);
            sc[ni][0] = p0; sc[ni][1] = p1; sc[ni][2] = p2; sc[ni][3] = p3;
            rs0 += p0 + p1; rs8 += p2 + p3;
        }
        rs0 += __shfl_xor_sync(0xffffffff, rs0, 1);
        rs0 += __shfl_xor_sync(0xffffffff, rs0, 2);
        rs8 += __shfl_xor_sync(0xffffffff, rs8, 1);
        rs8 += __shfl_xor_sync(0xffffffff, rs8, 2);
        l0 = l0*al0 + rs0;
        l8 = l8*al8 + rs8;
        #pragma unroll
        for (int ni = 0; ni < 8; ni++) {
            Oc[ni][0] *= al0; Oc[ni][1] *= al0;
            Oc[ni][2] *= al8; Oc[ni][3] *= al8;
        }

        uint32_t ph[4][4], pl[4][4];
        #pragma unroll
        for (int ks2 = 0; ks2 < 4; ks2++) {
            float x0 = sc[2*ks2][0],   x1 = sc[2*ks2][1];
            float x2 = sc[2*ks2][2],   x3 = sc[2*ks2][3];
            float y0 = sc[2*ks2+1][0], y1 = sc[2*ks2+1][1];
            float y2 = sc[2*ks2+1][2], y3 = sc[2*ks2+1][3];
            float hx0 = __bfloat162float(__float2bfloat16_rn(x0));
            float hx1 = __bfloat162float(__float2bfloat16_rn(x1));
            float hx2 = __bfloat162float(__float2bfloat16_rn(x2));
            float hx3 = __bfloat162float(__float2bfloat16_rn(x3));
            float hy0 = __bfloat162float(__float2bfloat16_rn(y0));
            float hy1 = __bfloat162float(__float2bfloat16_rn(y1));
            float hy2 = __bfloat162float(__float2bfloat16_rn(y2));
            float hy3 = __bfloat162float(__float2bfloat16_rn(y3));
            ph[ks2][0] = pack_bf2(hx0, hx1);
            ph[ks2][1] = pack_bf2(hx2, hx3);
            ph[ks2][2] = pack_bf2(hy0, hy1);
            ph[ks2][3] = pack_bf2(hy2, hy3);
            pl[ks2][0] = pack_bf2(x0 - hx0, x1 - hx1);
            pl[ks2][1] = pack_bf2(x2 - hx2, x3 - hx3);
            pl[ks2][2] = pack_bf2(y0 - hy0, y1 - hy1);
            pl[ks2][3] = pack_bf2(y2 - hy2, y3 - hy3);
        }

        #pragma unroll
        for (int ks2 = 0; ks2 < 4; ks2++)
            #pragma unroll
            for (int ni = 0; ni < 8; ni++) {
                int nr = ni*8 + r0;
                mma16816(Oc[ni], ph[ks2], Vt[nr][cq + 8*ks2], Vt[nr][cq + 8*ks2 + 4]);
            }
        #pragma unroll
        for (int ks2 = 0; ks2 < 4; ks2++)
            #pragma unroll
            for (int ni = 0; ni < 8; ni++) {
                int nr = ni*8 + r0;
                mma16816(Oc[ni], ph[ks2], Vt[nr][32 + cq + 8*ks2],
                         Vt[nr][32 + cq + 8*ks2 + 4]);
            }
        #pragma unroll
        for (int ks2 = 0; ks2 < 4; ks2++)
            #pragma unroll
            for (int ni = 0; ni < 8; ni++) {
                int nr = ni*8 + r0;
                mma16816(Oc[ni], pl[ks2], Vt[nr][cq + 8*ks2], Vt[nr][cq + 8*ks2 + 4]);
            }
        __syncthreads();
    }

    float i0 = 1.f / l0, i8 = 1.f / l8;
    #pragma unroll
    for (int ni = 0; ni < 8; ni++) {
        int cc = col0 + ni*8 + 2*cq;
        float2 w0 = {Oc[ni][0]*i0, Oc[ni][1]*i0};
        float2 w8 = {Oc[ni][2]*i8, Oc[ni][3]*i8};
        *(float2*)(o + ((size_t)(qrow + r0    )*B_ + b)*oS + cc) = w0;
        *(float2*)(o + ((size_t)(qrow + r0 + 8)*B_ + b)*oS + cc) = w8;
    }
}

// -------- memory retrieval + delta (no attn dependency) -----------------------
__global__ __launch_bounds__(256) void mem_retrieve(
    const float* __restrict__ q, const float* __restrict__ kp,
    const float* __restrict__ vp, const float* __restrict__ memory,
    const float* __restrict__ mem_norm, int l,
    float* __restrict__ content, float* __restrict__ diff, float* __restrict__ cKout,
    int qS, int kvS)
{
    int bn = blockIdx.x;
    int b = bn / NH_, n = bn % NH_;
    int chunk = blockIdx.y;
    int t = threadIdx.x;

    __shared__ float Msh[DH_][DH_+1];
    __shared__ float normsh[DH_];
    __shared__ float cqsh[4][DH_];
    __shared__ float cksh[4][DH_];

    const float* Mg = memory + ((size_t)(l*B_ + b)*NH_ + n)*DH_*DH_;
    for (int idx = t; idx < DH_*DH_; idx += 256) Msh[idx >> 6][idx & 63] = Mg[idx];
    if (t < DH_) normsh[t] = mem_norm[((size_t)(l*B_ + b)*NH_ + n)*DH_ + t];
    __syncthreads();

    int g = t >> 6, d = t & 63;
    int col = n * DH_;
    for (int it = 0; it < 32; ++it) {
        int s = chunk*128 + it*4 + g;
        size_t row = (size_t)(s*B_ + b);
        float qvl = q [row*qS  + col + d];
        float vvl = vp[row*kvS + col + d];
        float cq = qvl > 0.f ? qvl + 1.f : __expf(qvl);
        float ck = vvl > 0.f ? vvl + 1.f : __expf(vvl);
        cqsh[g][d] = cq; cksh[g][d] = ck;
        __syncthreads();
        float accA = 0.f, accB = 0.f, denQ = 0.f, denK = 0.f;
        #pragma unroll 8
        for (int kk = 0; kk < DH_; kk++) {
            float mq = Msh[kk][d];
            accA += cqsh[g][kk] * mq;
            accB += cksh[g][kk] * mq;
            denQ += cqsh[g][kk] * normsh[kk];
            denK += cksh[g][kk] * normsh[kk];
        }
        size_t oidx = row*D_ + col + d;
        content[oidx] = accA / denQ;
        diff[oidx]    = kp[row*kvS + col + d] - accB / denK;
        cKout[oidx]   = ck;
        __syncthreads();
    }
}

// -------- memory update: newM[k][v] = M[k][v] + sum_s cK[s,k]*diff[s,v] ------
__global__ __launch_bounds__(256) void mem_update(
    const float* __restrict__ cK, const float* __restrict__ diff,
    const float* __restrict__ memory, int l, float* __restrict__ outM)
{
    int bn = blockIdx.x;
    int b = bn / NH_, n = bn % NH_;
    __shared__ float aS[16][DH_];
    __shared__ float bS[16][DH_];
    int t = threadIdx.x;
    int tx = t & 15, ty = t >> 4;
    float acc[4][4] = {};
    int col = n * DH_;
    int r  = t >> 4;
    int c4 = (t & 15) * 4;
    for (int s0 = 0; s0 < S_; s0 += 16) {
        size_t row = (size_t)((s0 + r)*B_ + b);
        *(float4*)&aS[r][c4] = *(const float4*)(cK   + row*D_ + col + c4);
        *(float4*)&bS[r][c4] = *(const float4*)(diff + row*D_ + col + c4);
        __syncthreads();
        #pragma unroll
        for (int ss = 0; ss < 16; ss++) {
            float a[4], bb[4];
            #pragma unroll
            for (int u = 0; u < 4; u++) { a[u] = aS[ss][ty*4+u]; bb[u] = bS[ss][tx*4+u]; }
            #pragma unroll
            for (int i = 0; i < 4; i++)
                #pragma unroll
                for (int j = 0; j < 4; j++)
                    acc[i][j] = fmaf(a[i], bb[j], acc[i][j]);
        }
        __syncthreads();
    }
    const float* Mg = memory + ((size_t)(l*B_ + b)*NH_ + n)*DH_*DH_;
    float*       Og = outM   + ((size_t)(l*B_ + b)*NH_ + n)*DH_*DH_;
    #pragma unroll
    for (int i = 0; i < 4; i++)
        #pragma unroll
        for (int j = 0; j < 4; j++) {
            int kk = ty*4 + i, vv = tx*4 + j;
            Og[kk*DH_ + vv] = Mg[kk*DH_ + vv] + acc[i][j];
        }
}

// -------- norm update: outN = mem_norm + sum_s cK (parallel over s) ----------
__global__ __launch_bounds__(512) void norm_update(
    const float* __restrict__ cK, const float* __restrict__ mem_norm, int l,
    float* __restrict__ outN)
{
    int bn = blockIdx.x;
    int b = bn / NH_, n = bn % NH_;
    int t = threadIdx.x;
    int d = t & 63, sg = t >> 6;
    int col = n * DH_;
    float acc = 0.f;
    for (int s = sg; s < S_; s += 8)
        acc += cK[(size_t)(s*B_ + b)*D_ + col + d];
    __shared__ float red[512];
    red[t] = acc; __syncthreads();
    if (t < 256) red[t] += red[t + 256]; __syncthreads();
    if (t < 128) red[t] += red[t + 128]; __syncthreads();
    if (t < 64) {
        size_t o = ((size_t)(l*B_ + b)*NH_ + n)*DH_ + t;
        outN[o] = mem_norm[o] + red[t] + red[t + 64];
    }
}

// -------- layernorm with residual (single-pass sum/sumsq, shuffle) ------------
__global__ __launch_bounds__(256) void ln_kernel(
    const float* __restrict__ res, const float* __restrict__ y,
    const float* __restrict__ g, const float* __restrict__ bb,
    float* __restrict__ out)
{
    int row = blockIdx.x;
    int t = threadIdx.x, lane = t & 31, warp = t >> 5;
    __shared__ float ws[8], wss[8];
    size_t base = (size_t)row * D_;
    float x0 = res[base + t      ] + y[base + t      ];
    float x1 = res[base + t + 256] + y[base + t + 256];
    float x2 = res[base + t + 512] + y[base + t + 512];
    float s  = x0 + x1 + x2;
    float ss = x0*x0 + x1*x1 + x2*x2;
    #pragma unroll
    for (int off = 16; off > 0; off >>= 1) {
        s  += __shfl_xor_sync(0xffffffff, s,  off);
        ss += __shfl_xor_sync(0xffffffff, ss, off);
    }
    if (lane == 0) { ws[warp] = s; wss[warp] = ss; }
    __syncthreads();
    float S = 0.f, SS = 0.f;
    #pragma unroll
    for (int w = 0; w < 8; w++) { S += ws[w]; SS += wss[w]; }
    float mu  = S * (1.f / 768.f);
    float var = SS * (1.f / 768.f) - mu*mu;
    float inv = rsqrtf(var + 1e-5f);
    out[base + t      ] = (x0 - mu) * inv * g[t      ] + bb[t      ];
    out[base + t + 256] = (x1 - mu) * inv * g[t + 256] + bb[t + 256];
    out[base + t + 512] = (x2 - mu) * inv * g[t + 512] + bb[t + 512];
}

// ------------------------------- launcher -------------------------------------
extern "C" void kernel_launch(void* const* d_in, const int* in_sizes, int n_in,
                              void* d_out, int out_size)
{
    const int*   inp      = (const int*)  d_in[0];
    const float* word_emb = (const float*)d_in[1];
    const float* Wq       = (const float*)d_in[2];
    const float* Wkv      = (const float*)d_in[3];
    const float* Wo       = (const float*)d_in[4];
    const float* ln1g     = (const float*)d_in[5];
    const float* ln1b     = (const float*)d_in[6];
    const float* ffW1     = (const float*)d_in[7];
    const float* ffb1     = (const float*)d_in[8];
    const float* ffW2     = (const float*)d_in[9];
    const float* ffb2     = (const float*)d_in[10];
    const float* ln2g     = (const float*)d_in[11];
    const float* ln2b     = (const float*)d_in[12];
    const float* memory   = (const float*)d_in[13];
    const float* mem_norm = (const float*)d_in[14];

    float* out  = (float*)d_out;
    float* outH = out;                         // (S,B,D)
    float* outM = out + (size_t)SB_*D_;        // (L,B,NH,DH,DH)
    float* outN = outM + (size_t)L_*B_*NH_*DH_*DH_;  // (L,B,NH,DH)

    float *h, *q, *kv, *attn, *content, *cK, *diff, *ff, *out1, *wo;
    cudaGetSymbolAddress((void**)&h,       g_h);
    cudaGetSymbolAddress((void**)&q,       g_q);
    cudaGetSymbolAddress((void**)&kv,      g_kv);
    cudaGetSymbolAddress((void**)&attn,    g_attn);
    cudaGetSymbolAddress((void**)&content, g_content);
    cudaGetSymbolAddress((void**)&cK,      g_cK);
    cudaGetSymbolAddress((void**)&diff,    g_diff);
    cudaGetSymbolAddress((void**)&ff,      g_ff);
    cudaGetSymbolAddress((void**)&out1,    g_out1);
    cudaGetSymbolAddress((void**)&wo,      g_wo);

    // side stream + events, created once (outside any capture: first call is
    // the non-captured correctness run)
    static cudaStream_t s1 = nullptr;
    static cudaEvent_t evA = nullptr, evB = nullptr, evC = nullptr, evD = nullptr;
    if (!s1) {
        cudaStreamCreateWithFlags(&s1, cudaStreamNonBlocking);
        cudaEventCreateWithFlags(&evA, cudaEventDisableTiming);
        cudaEventCreateWithFlags(&evB, cudaEventDisableTiming);
        cudaEventCreateWithFlags(&evC, cudaEventDisableTiming);
        cudaEventCreateWithFlags(&evD, cudaEventDisableTiming);
    }

    const float gate = 1.0f / (1.0f + expf(-0.01f));

    embed_kernel<<<SB_, 256>>>(inp, word_emb, h);

    for (int l = 0; l < L_; l++) {
        // merged q|kv projection (one 576-block launch)
        gemm_qkv<<<dim3(18, SB_/128), 256>>>(h, Wq + (size_t)l*D_*D_,
                                             Wkv + (size_t)l*2*D_*D_, q, kv, D_);
        // fork side stream after qkv
        cudaEventRecord(evA, 0);
        cudaStreamWaitEvent(s1, evA, 0);
        if (l > 0) cudaStreamWaitEvent(s1, evC, 0);   // content free after Wo(l-1)

        // main stream: local causal attention
        attn_mma<<<dim3(8, B_*NH_), 256>>>(q, kv /*k*/, kv + D_ /*v*/, attn,
                                           D_, 2*D_, D_);

        // side stream: memory path (content/diff/cK, M & norm updates)
        mem_retrieve<<<dim3(B_*NH_, 8), 256, 0, s1>>>(q, kv /*k*/, kv + D_ /*v*/,
                                                      memory, mem_norm, l,
                                                      content, diff, cK, D_, 2*D_);
        cudaEventRecord(evB, s1);
        mem_update<<<B_*NH_, 256, 0, s1>>>(cK, diff, memory, l, outM);
        norm_update<<<B_*NH_, 512, 0, s1>>>(cK, mem_norm, l, outN);
        cudaEventRecord(evD, s1);

        // main stream: Wo projection with fused gated combine
        cudaStreamWaitEvent(0, evB, 0);               // content ready
        gemm_wo<<<dim3(D_/128, SB_/128), 256>>>(content, attn, gate,
                                                Wo + (size_t)l*D_*D_, wo, D_, D_);
        cudaEventRecord(evC, 0);

        // ln1: out1 = LN(h + wo)
        ln_kernel<<<SB_, 256>>>(h, wo, ln1g + l*D_, ln1b + l*D_, out1);
        // ff1 = relu(out1 @ W1^T + b1)
        gemm_bf16s<<<dim3(DI_/128, SB_/128), 256>>>(out1, ffW1 + (size_t)l*DI_*D_,
                                                    ffb1 + l*DI_, ff, DI_, D_, 1);
        // ff2 = ff1 @ W2^T + b2 -> q buffer (dead until next layer's qkv)
        gemm_bf16s<<<dim3(D_/128, SB_/128), 256>>>(ff, ffW2 + (size_t)l*D_*DI_,
                                                   ffb2 + l*D_, q, D_, DI_, 2);
        // ln2: h = LN(out1 + ff2)
        ln_kernel<<<SB_, 256>>>(out1, q, ln2g + l*D_, ln2b + l*D_, h);
    }

    // join side stream before finishing
    cudaStreamWaitEvent(0, evD, 0);
    cudaMemcpyAsync(outH, h, (size_t)SB_*D_*sizeof(float),
                    cudaMemcpyDeviceToDevice);
}